// round 7
// baseline (speedup 1.0000x reference)
#include <cuda_runtime.h>
#include <cuda_bf16.h>
#include <math.h>
#include <stdint.h>

#define NN 100000
#define NE 3200000
#define H  256
#define NC 40
#define NL 8
#define MPAD 100096          // 782 * 128
#define GRID_M 782
#define BIGK (1 << 30)

// ---------------- device scratch (no allocations allowed) ------------------
__device__ int   g_deg[NN];
__device__ int   g_cur[NN];
__device__ int   g_rowptr[NN + 1];
__device__ int   g_bsums[128];
__device__ int   g_csrc[NE];
__device__ float g_cw[NE];

__device__ float g_h0f[MPAD * H];
__device__ float g_hf [MPAD * H];
__device__ float g_hif[MPAD * H];
__device__ float g_df [MPAD * H];
__device__ float g_cpf[MPAD * H];     // conv partial: h0 @ W_bot

__device__ __nv_bfloat16 g_bx_hi[MPAD * 512];
__device__ __nv_bfloat16 g_bx_lo[MPAD * 512];
__device__ __nv_bfloat16 g_bh0_hi[MPAD * H];
__device__ __nv_bfloat16 g_bh0_lo[MPAD * H];
__device__ __nv_bfloat16 g_bhi_hi[MPAD * H];
__device__ __nv_bfloat16 g_bhi_lo[MPAD * H];
__device__ __nv_bfloat16 g_bdA_hi[MPAD * H];
__device__ __nv_bfloat16 g_bdA_lo[MPAD * H];
__device__ __nv_bfloat16 g_bdB_hi[MPAD * H];
__device__ __nv_bfloat16 g_bdB_lo[MPAD * H];

// weights, pre-transposed to [N=256][K] row-major, bf16 split
__device__ __nv_bfloat16 g_wt9_hi[9 * H * 512];   // fc + 8 conv (K=512)
__device__ __nv_bfloat16 g_wt9_lo[9 * H * 512];
__device__ __nv_bfloat16 g_wtd_hi[NL * H * H];    // dyn effective (K=256)
__device__ __nv_bfloat16 g_wtd_lo[NL * H * H];

// ---------------- helpers --------------------------------------------------
__device__ __forceinline__ uint32_t smem_u32(const void* p) {
    uint32_t a;
    asm("{ .reg .u64 t; cvta.to.shared.u64 t, %1; cvt.u32.u64 %0, t; }" : "=r"(a) : "l"(p));
    return a;
}
#define SW128(o) ((o) ^ (((o) >> 3) & 0x70))

__device__ __forceinline__ void cpasync16(uint32_t dst, const void* src, int srcsize) {
    uint64_t g = __cvta_generic_to_global(src);
    asm volatile("cp.async.cg.shared.global [%0], [%1], 16, %2;"
                 :: "r"(dst), "l"(g), "r"(srcsize) : "memory");
}
#define CP_COMMIT() asm volatile("cp.async.commit_group;" ::: "memory")
#define CP_WAIT1()  asm volatile("cp.async.wait_group 1;" ::: "memory")
#define CP_WAIT0()  asm volatile("cp.async.wait_group 0;" ::: "memory")

__device__ __forceinline__ void ldx4(uint32_t* r, uint32_t addr) {
    asm volatile("ldmatrix.sync.aligned.m8n8.x4.shared.b16 {%0,%1,%2,%3}, [%4];"
                 : "=r"(r[0]), "=r"(r[1]), "=r"(r[2]), "=r"(r[3]) : "r"(addr));
}
__device__ __forceinline__ void ldx2(uint32_t* r, uint32_t addr) {
    asm volatile("ldmatrix.sync.aligned.m8n8.x2.shared.b16 {%0,%1}, [%2];"
                 : "=r"(r[0]), "=r"(r[1]) : "r"(addr));
}
__device__ __forceinline__ void mma16816(float* c, const uint32_t* a, const uint32_t* b) {
    asm volatile("mma.sync.aligned.m16n8k16.row.col.f32.bf16.bf16.f32 "
                 "{%0,%1,%2,%3}, {%4,%5,%6,%7}, {%8,%9}, {%0,%1,%2,%3};"
                 : "+f"(c[0]), "+f"(c[1]), "+f"(c[2]), "+f"(c[3])
                 : "r"(a[0]), "r"(a[1]), "r"(a[2]), "r"(a[3]), "r"(b[0]), "r"(b[1]));
}

// small buffer (BN=128): [Ahi 16K][Alo 16K][Bhi 16K][Blo 16K] = 64KB
#define SMEM_SMALL 65536
// big buffer (BN=256): [Ahi 16K][Alo 16K][Bhi 32K][Blo 32K] = 96KB, x2
#define BIGBUF 98304
#define SMEM_BIG (2 * BIGBUF)
#define BOFF_BHI 32768
#define BOFF_BLO 65536

// ---------------- CSR build ------------------------------------------------
__global__ void k_zero() {
    int i = blockIdx.x * blockDim.x + threadIdx.x;
    if (i < NN) { g_deg[i] = 0; g_cur[i] = 0; }
}
__global__ void k_hist(const int* __restrict__ dst) {
    int e = blockIdx.x * blockDim.x + threadIdx.x;
    if (e < NE) atomicAdd(&g_deg[dst[e]], 1);
}
__global__ void k_scan1() {
    __shared__ int sh[256];
    int b = blockIdx.x, t = threadIdx.x;
    int base = b * 1024 + t * 4;
    int v[4], loc[4];
#pragma unroll
    for (int j = 0; j < 4; j++) { int idx = base + j; v[j] = (idx < NN) ? g_deg[idx] : 0; }
    loc[0] = v[0];
#pragma unroll
    for (int j = 1; j < 4; j++) loc[j] = loc[j - 1] + v[j];
    sh[t] = loc[3];
    __syncthreads();
    for (int off = 1; off < 256; off <<= 1) {
        int x = (t >= off) ? sh[t - off] : 0;
        __syncthreads();
        sh[t] += x;
        __syncthreads();
    }
    int pre = (t > 0) ? sh[t - 1] : 0;
#pragma unroll
    for (int j = 0; j < 4; j++) { int idx = base + j; if (idx < NN) g_rowptr[idx + 1] = pre + loc[j]; }
    if (t == 255) g_bsums[b] = sh[255];
}
__global__ void k_scan2(int nb) {
    __shared__ int sh[128];
    int t = threadIdx.x;
    sh[t] = (t < nb) ? g_bsums[t] : 0;
    __syncthreads();
    for (int off = 1; off < 128; off <<= 1) {
        int x = (t >= off) ? sh[t - off] : 0;
        __syncthreads();
        sh[t] += x;
        __syncthreads();
    }
    g_bsums[t] = sh[t];
}
__global__ void k_scan3() {
    int b = blockIdx.x, t = threadIdx.x;
    int add = (b > 0) ? g_bsums[b - 1] : 0;
#pragma unroll
    for (int j = 0; j < 4; j++) {
        int idx = b * 1024 + t * 4 + j;
        if (idx < NN) g_rowptr[idx + 1] += add;
    }
    if (b == 0 && t == 0) g_rowptr[0] = 0;
}
__global__ void k_scatter(const int* __restrict__ src, const int* __restrict__ dst,
                          const float* __restrict__ w) {
    int e = blockIdx.x * blockDim.x + threadIdx.x;
    if (e < NE) {
        int d = dst[e];
        int pos = g_rowptr[d] + atomicAdd(&g_cur[d], 1);
        g_csrc[pos] = src[e];
        g_cw[pos] = w[e];
    }
}

// ---------------- weight prep (transpose + bf16 split) ---------------------
__device__ __forceinline__ void bsplit(float v, __nv_bfloat16& hi, __nv_bfloat16& lo) {
    hi = __float2bfloat16_rn(v);
    lo = __float2bfloat16_rn(v - __bfloat162float(hi));
}
__global__ void k_wprep9(const float* __restrict__ Wfc, const float* __restrict__ convw) {
    int idx = blockIdx.x * blockDim.x + threadIdx.x;
    if (idx >= 9 * 512 * 256) return;
    int m = idx / (512 * 256);
    int r = idx - m * 512 * 256;
    int k = r / 256, n = r - k * 256;
    float v = (m == 0) ? Wfc[r] : convw[(m - 1) * 512 * 256 + r];
    __nv_bfloat16 hi, lo; bsplit(v, hi, lo);
    size_t o = (size_t)m * 256 * 512 + (size_t)n * 512 + k;
    g_wt9_hi[o] = hi; g_wt9_lo[o] = lo;
}
__global__ void k_wprepd(const float* __restrict__ dynw) {
    int idx = blockIdx.x * blockDim.x + threadIdx.x;
    if (idx >= NL * 256 * 256) return;
    int i = idx / (256 * 256);
    int r = idx - i * 256 * 256;
    int k = r / 256, n = r - k * 256;
    const float* base = dynw + (size_t)i * 512 * 256;
    float v = base[k * 256 + n] - base[(k + 256) * 256 + n];
    __nv_bfloat16 hi, lo; bsplit(v, hi, lo);
    size_t o = (size_t)i * 256 * 256 + (size_t)n * 256 + k;
    g_wtd_hi[o] = hi; g_wtd_lo[o] = lo;
}
__global__ void k_convx(const float* __restrict__ x) {
    int idx = blockIdx.x * blockDim.x + threadIdx.x;
    if (idx >= NN * 512) return;
    __nv_bfloat16 hi, lo; bsplit(x[idx], hi, lo);
    g_bx_hi[idx] = hi; g_bx_lo[idx] = lo;
}

// ============ BIG GEMM (BN=256, double-buffered, 192KB smem) ================
// MODE 0 fc  : v=relu(acc+bias); write C(hf), C2(h0f), Chi/Clo(bh0)
// MODE 1 conv: v=relu(theta*(acc+Cpart)+(1-theta)*(0.9*Ehi+0.1*Eh0)+Eh); write C
template <int MODE>
__device__ void gemm_big(
           int by,
           const __nv_bfloat16* __restrict__ Ah_, const __nv_bfloat16* __restrict__ Al_, int sA,
           int K,
           const __nv_bfloat16* __restrict__ Bh, const __nv_bfloat16* __restrict__ Bl, int Bst,
           float* __restrict__ C, const float* __restrict__ bias,
           const float* __restrict__ Ehi, const float* __restrict__ Eh0, const float* __restrict__ Eh,
           const float* __restrict__ Cpart, float theta,
           __nv_bfloat16* __restrict__ Chi, __nv_bfloat16* __restrict__ Clo,
           float* __restrict__ C2)
{
    extern __shared__ char smc[];
    uint32_t sb = smem_u32(smc);
    int t = threadIdx.x, lane = t & 31, wid = t >> 5;
    int widm = wid >> 2, widn = wid & 3;   // 2 x 4 warps; warp tile 64x64
    int bm0 = by * 128;

    float acc[4][8][4];
#pragma unroll
    for (int a = 0; a < 4; a++)
#pragma unroll
        for (int b = 0; b < 8; b++)
#pragma unroll
            for (int c = 0; c < 4; c++) acc[a][b][c] = 0.f;

    const int nc = K / 64;

    int mi = lane >> 3;
    int arow_off = (lane & 7) + ((mi & 1) << 3);
    int akcol = (mi >> 1) << 4;
    int brow_off = (lane & 7);
    int bkcol = ((lane >> 3) & 1) << 4;

    auto load_chunk = [&](int ch, int buf) {
        uint32_t bb = sb + buf * BIGBUF;
        int kk0 = ch * 64;
#pragma unroll
        for (int j = 0; j < 4; j++) {         // A: 128 rows x 128B
            int idx = t + j * 256;
            int r = idx >> 3, c16 = idx & 7;
            uint32_t d = SW128(r * 128 + c16 * 16);
            int grow = bm0 + r;
            int kk = kk0 + c16 * 8;
            int pred = 16;
            if (grow >= NN) { grow = 0; pred = 0; }
            cpasync16(bb + d,         Ah_ + (size_t)grow * sA + kk, pred);
            cpasync16(bb + 16384 + d, Al_ + (size_t)grow * sA + kk, pred);
        }
#pragma unroll
        for (int j = 0; j < 8; j++) {         // B: 256 rows x 128B
            int idx = t + j * 256;
            int r = idx >> 3, c16 = idx & 7;
            uint32_t d = SW128(r * 128 + c16 * 16);
            size_t bo = (size_t)r * Bst + kk0 + c16 * 8;
            cpasync16(bb + BOFF_BHI + d, Bh + bo, 16);
            cpasync16(bb + BOFF_BLO + d, Bl + bo, 16);
        }
        CP_COMMIT();
    };

    load_chunk(0, 0);
    for (int c = 0; c < nc; c++) {
        if (c + 1 < nc) { load_chunk(c + 1, (c + 1) & 1); CP_WAIT1(); }
        else            { CP_WAIT0(); }
        __syncthreads();
        uint32_t bb = sb + (c & 1) * BIGBUF;
#pragma unroll
        for (int ks = 0; ks < 4; ks++) {
            int kb = ks * 32;
            uint32_t Bh2[8][2], Bl2[8][2];
#pragma unroll
            for (int nt = 0; nt < 8; nt++) {
                int row = widn * 64 + nt * 8 + brow_off;
                uint32_t bd = bb + BOFF_BHI + SW128(row * 128 + kb + bkcol);
                ldx2(Bh2[nt], bd);
                ldx2(Bl2[nt], bd + 32768);
            }
#pragma unroll
            for (int mt = 0; mt < 4; mt++) {
                uint32_t Ah[4], Al[4];
                int row = widm * 64 + mt * 16 + arow_off;
                uint32_t ad = bb + SW128(row * 128 + kb + akcol);
                ldx4(Ah, ad);
                ldx4(Al, ad + 16384);
#pragma unroll
                for (int nt = 0; nt < 8; nt++) {
                    mma16816(acc[mt][nt], Ah, Bh2[nt]);
                    mma16816(acc[mt][nt], Ah, Bl2[nt]);
                    mma16816(acc[mt][nt], Al, Bh2[nt]);
                }
            }
        }
        __syncthreads();
    }

    // ---- epilogue ----
#pragma unroll
    for (int mt = 0; mt < 4; mt++) {
#pragma unroll
        for (int nt = 0; nt < 8; nt++) {
            int cb = widn * 64 + nt * 8 + (lane & 3) * 2;
#pragma unroll
            for (int half = 0; half < 2; half++) {
                int row = bm0 + widm * 64 + mt * 16 + (lane >> 2) + half * 8;
                if (row >= NN) continue;
                size_t rb = (size_t)row * H + cb;
                float v0 = acc[mt][nt][half * 2 + 0];
                float v1 = acc[mt][nt][half * 2 + 1];
                if (MODE == 0) {
                    v0 = fmaxf(v0 + bias[cb], 0.f);
                    v1 = fmaxf(v1 + bias[cb + 1], 0.f);
                } else {
                    float2 cp = *(const float2*)(Cpart + rb);
                    float2 e1 = *(const float2*)(Ehi + rb);
                    float2 e2 = *(const float2*)(Eh0 + rb);
                    float2 e3 = *(const float2*)(Eh + rb);
                    v0 = fmaxf(theta * (v0 + cp.x) + (1.f - theta) * (0.9f * e1.x + 0.1f * e2.x) + e3.x, 0.f);
                    v1 = fmaxf(theta * (v1 + cp.y) + (1.f - theta) * (0.9f * e1.y + 0.1f * e2.y) + e3.y, 0.f);
                }
                *(float2*)(C + rb) = make_float2(v0, v1);
                if (MODE == 0) {
                    *(float2*)(C2 + rb) = make_float2(v0, v1);
                    union { uint32_t u; __nv_bfloat16 b[2]; } ph_, pl_;
                    __nv_bfloat16 h0b = __float2bfloat16_rn(v0);
                    __nv_bfloat16 h1b = __float2bfloat16_rn(v1);
                    ph_.b[0] = h0b; ph_.b[1] = h1b;
                    pl_.b[0] = __float2bfloat16_rn(v0 - __bfloat162float(h0b));
                    pl_.b[1] = __float2bfloat16_rn(v1 - __bfloat162float(h1b));
                    *(uint32_t*)(Chi + rb) = ph_.u;
                    *(uint32_t*)(Clo + rb) = pl_.u;
                }
            }
        }
    }
}

template <int MODE>
__global__ void __launch_bounds__(256, 1)
k_gemm_big(const __nv_bfloat16* Ah_, const __nv_bfloat16* Al_, int sA, int K,
           const __nv_bfloat16* Bh, const __nv_bfloat16* Bl, int Bst,
           float* C, const float* bias,
           const float* Ehi, const float* Eh0, const float* Eh,
           const float* Cpart, float theta,
           __nv_bfloat16* Chi, __nv_bfloat16* Clo, float* C2)
{
    gemm_big<MODE>(blockIdx.x, Ah_, Al_, sA, K, Bh, Bl, Bst, C, bias,
                   Ehi, Eh0, Eh, Cpart, theta, Chi, Clo, C2);
}

// ============ SMALL GEMM (BN=128, single buffer 64KB) =======================
// MODE 2 dyn     : v=relu(acc+bias)+res*Eh0; write C(df), Chi/Clo
// MODE 3 convpart: C = acc (f32)
template <int MODE>
__device__ void gemm_small(
           int bx, int by,
           const __nv_bfloat16* __restrict__ Ah_, const __nv_bfloat16* __restrict__ Al_, int sA,
           int K,
           const __nv_bfloat16* __restrict__ Bh, const __nv_bfloat16* __restrict__ Bl, int Bst,
           float* __restrict__ C, const float* __restrict__ bias,
           const float* __restrict__ Eh0, float res_scale,
           __nv_bfloat16* __restrict__ Chi, __nv_bfloat16* __restrict__ Clo)
{
    extern __shared__ char smc[];
    uint32_t sb = smem_u32(smc);
    int t = threadIdx.x, lane = t & 31, wid = t >> 5;
    int widm = wid >> 2, widn = wid & 3;
    int bn0 = bx * 128;
    int bm0 = by * 128;

    float acc[4][4][4];
#pragma unroll
    for (int a = 0; a < 4; a++)
#pragma unroll
        for (int b = 0; b < 4; b++)
#pragma unroll
            for (int c = 0; c < 4; c++) acc[a][b][c] = 0.f;

    const int nc = K / 64;

    int mi = lane >> 3;
    int arow_off = (lane & 7) + ((mi & 1) << 3);
    int akcol = (mi >> 1) << 4;
    int brow_off = (lane & 7);
    int bkcol = ((lane >> 3) & 1) << 4;

    for (int c = 0; c < nc; c++) {
        {
            int kk0 = c * 64;
#pragma unroll
            for (int j = 0; j < 4; j++) {
                int idx = t + j * 256;
                int r = idx >> 3, c16 = idx & 7;
                uint32_t d = SW128(r * 128 + c16 * 16);
                int grow = bm0 + r;
                int kk = kk0 + c16 * 8;
                int pred = 16;
                if (grow >= NN) { grow = 0; pred = 0; }
                cpasync16(sb + d,         Ah_ + (size_t)grow * sA + kk, pred);
                cpasync16(sb + 16384 + d, Al_ + (size_t)grow * sA + kk, pred);
                size_t bo = (size_t)(bn0 + r) * Bst + kk0 + c16 * 8;
                cpasync16(sb + 32768 + d, Bh + bo, 16);
                cpasync16(sb + 49152 + d, Bl + bo, 16);
            }
            CP_COMMIT();
        }
        CP_WAIT0();
        __syncthreads();
#pragma unroll
        for (int ks = 0; ks < 4; ks++) {
            int kb = ks * 32;
            uint32_t Bh2[4][2], Bl2[4][2];
#pragma unroll
            for (int nt = 0; nt < 4; nt++) {
                int row = widn * 32 + nt * 8 + brow_off;
                uint32_t bd = sb + 32768 + SW128(row * 128 + kb + bkcol);
                ldx2(Bh2[nt], bd);
                ldx2(Bl2[nt], bd + 16384);
            }
#pragma unroll
            for (int mt = 0; mt < 4; mt++) {
                uint32_t Ah[4], Al[4];
                int row = widm * 64 + mt * 16 + arow_off;
                uint32_t ad = sb + SW128(row * 128 + kb + akcol);
                ldx4(Ah, ad);
                ldx4(Al, ad + 16384);
#pragma unroll
                for (int nt = 0; nt < 4; nt++) {
                    mma16816(acc[mt][nt], Ah, Bh2[nt]);
                    mma16816(acc[mt][nt], Ah, Bl2[nt]);
                    mma16816(acc[mt][nt], Al, Bh2[nt]);
                }
            }
        }
        __syncthreads();
    }

#pragma unroll
    for (int mt = 0; mt < 4; mt++) {
#pragma unroll
        for (int nt = 0; nt < 4; nt++) {
            int cb = bn0 + widn * 32 + nt * 8 + (lane & 3) * 2;
#pragma unroll
            for (int half = 0; half < 2; half++) {
                int row = bm0 + widm * 64 + mt * 16 + (lane >> 2) + half * 8;
                if (row >= NN) continue;
                size_t rb = (size_t)row * H + cb;
                float v0 = acc[mt][nt][half * 2 + 0];
                float v1 = acc[mt][nt][half * 2 + 1];
                if (MODE == 2) {
                    float2 e2 = *(const float2*)(Eh0 + rb);
                    v0 = fmaxf(v0 + bias[cb], 0.f) + res_scale * e2.x;
                    v1 = fmaxf(v1 + bias[cb + 1], 0.f) + res_scale * e2.y;
                }
                *(float2*)(C + rb) = make_float2(v0, v1);
                if (MODE == 2) {
                    union { uint32_t u; __nv_bfloat16 b[2]; } ph_, pl_;
                    __nv_bfloat16 h0b = __float2bfloat16_rn(v0);
                    __nv_bfloat16 h1b = __float2bfloat16_rn(v1);
                    ph_.b[0] = h0b; ph_.b[1] = h1b;
                    pl_.b[0] = __float2bfloat16_rn(v0 - __bfloat162float(h0b));
                    pl_.b[1] = __float2bfloat16_rn(v1 - __bfloat162float(h1b));
                    *(uint32_t*)(Chi + rb) = ph_.u;
                    *(uint32_t*)(Clo + rb) = pl_.u;
                }
            }
        }
    }
}

// ---------------- SpMM block (device function) ------------------------------
__device__ void spmm_block(int node_base, const float* __restrict__ h,
                           float* __restrict__ hif,
                           __nv_bfloat16* __restrict__ bhih,
                           __nv_bfloat16* __restrict__ bhil) {
    int wid = threadIdx.x >> 5, lane = threadIdx.x & 31;
    int node = node_base + wid;
    if (node >= NN) return;
    int s0 = g_rowptr[node], s1 = g_rowptr[node + 1];
    float4 a0 = make_float4(0.f, 0.f, 0.f, 0.f);
    float4 a1 = make_float4(0.f, 0.f, 0.f, 0.f);
    const float4* h4 = (const float4*)h;
    int e = s0;
    for (; e + 3 < s1; e += 4) {
        int si[4]; float w[4];
#pragma unroll
        for (int u = 0; u < 4; u++) { si[u] = g_csrc[e + u]; w[u] = g_cw[e + u]; }
        float4 v0[4], v1[4];
#pragma unroll
        for (int u = 0; u < 4; u++) {
            const float4* p = h4 + (size_t)si[u] * 64;
            v0[u] = __ldg(p + lane);
            v1[u] = __ldg(p + lane + 32);
        }
#pragma unroll
        for (int u = 0; u < 4; u++) {
            a0.x += w[u] * v0[u].x; a0.y += w[u] * v0[u].y;
            a0.z += w[u] * v0[u].z; a0.w += w[u] * v0[u].w;
            a1.x += w[u] * v1[u].x; a1.y += w[u] * v1[u].y;
            a1.z += w[u] * v1[u].z; a1.w += w[u] * v1[u].w;
        }
    }
    for (; e < s1; e++) {
        int sA = g_csrc[e];
        float wA = g_cw[e];
        const float4* pA = h4 + (size_t)sA * 64;
        float4 vA0 = __ldg(pA + lane), vA1 = __ldg(pA + lane + 32);
        a0.x += wA * vA0.x; a0.y += wA * vA0.y; a0.z += wA * vA0.z; a0.w += wA * vA0.w;
        a1.x += wA * vA1.x; a1.y += wA * vA1.y; a1.z += wA * vA1.z; a1.w += wA * vA1.w;
    }
    float4* op = (float4*)hif + (size_t)node * 64;
    op[lane] = a0;
    op[lane + 32] = a1;
    size_t rb = (size_t)node * H;
    union { uint2 u; __nv_bfloat16 b[4]; } ph_, pl_;
    float va[4] = {a0.x, a0.y, a0.z, a0.w};
#pragma unroll
    for (int i = 0; i < 4; i++) {
        __nv_bfloat16 hb = __float2bfloat16_rn(va[i]);
        ph_.b[i] = hb; pl_.b[i] = __float2bfloat16_rn(va[i] - __bfloat162float(hb));
    }
    *(uint2*)(bhih + rb + lane * 4) = ph_.u;
    *(uint2*)(bhil + rb + lane * 4) = pl_.u;
    float vb[4] = {a1.x, a1.y, a1.z, a1.w};
#pragma unroll
    for (int i = 0; i < 4; i++) {
        __nv_bfloat16 hb = __float2bfloat16_rn(vb[i]);
        ph_.b[i] = hb; pl_.b[i] = __float2bfloat16_rn(vb[i] - __bfloat162float(hb));
    }
    *(uint2*)(bhih + rb + 128 + lane * 4) = ph_.u;
    *(uint2*)(bhil + rb + 128 + lane * 4) = pl_.u;
}

// ---------------- fused SpMM + dyn-GEMM + conv-partial ----------------------
// 3128 gemm ids (even: dyn, odd: convpart) + 12500 spmm blocks; every 5th = gemm.
#define FUSED_GRID 15640
__global__ void __launch_bounds__(256, 2)
k_sd(const __nv_bfloat16* dinh, const __nv_bfloat16* dinl,
     const __nv_bfloat16* wdh, const __nv_bfloat16* wdl,
     float* df, const float* dynb, const float* h0f, float res_scale,
     __nv_bfloat16* douh, __nv_bfloat16* doul,
     const __nv_bfloat16* bh0h, const __nv_bfloat16* bh0l,
     const __nv_bfloat16* cwbh, const __nv_bfloat16* cwbl, float* cpf,
     const float* hf, float* hif, __nv_bfloat16* bhih, __nv_bfloat16* bhil)
{
    int bid = blockIdx.x;
    if (bid % 5 == 0) {
        int g = bid / 5;
        if (g < 3128) {
            int sub = g >> 1;
            int bx = sub & 1, by = sub >> 1;
            if ((g & 1) == 0)
                gemm_small<2>(bx, by, dinh, dinl, 256, 256, wdh, wdl, 256,
                              df, dynb, h0f, res_scale, douh, doul);
            else
                gemm_small<3>(bx, by, bh0h, bh0l, 256, 256, cwbh, cwbl, 512,
                              cpf, nullptr, nullptr, 0.f, nullptr, nullptr);
        }
    } else {
        int sid = bid - bid / 5 - 1;
        if (sid < NN / 8)
            spmm_block(sid * 8, hf, hif, bhih, bhil);
    }
}

// ---------------- LN cross + output ----------------------------------------
__device__ __forceinline__ float warp_sum(float v) {
#pragma unroll
    for (int off = 16; off; off >>= 1) v += __shfl_xor_sync(0xffffffffu, v, off);
    return v;
}

__global__ void __launch_bounds__(256) k_cross(
    const float* __restrict__ h, const float* __restrict__ d,
    const float* __restrict__ g1, const float* __restrict__ b1,
    const float* __restrict__ g2, const float* __restrict__ b2,
    float* __restrict__ crossbuf, float* __restrict__ cross_out)
{
    int row = blockIdx.x * 8 + (threadIdx.x >> 5);
    int lane = threadIdx.x & 31;
    if (row >= NN) return;
    size_t rb = (size_t)row * H;
    float hv[8], dv[8];
#pragma unroll
    for (int r = 0; r < 8; r++) {
        int k = lane + 32 * r;
        hv[r] = h[rb + k];
        dv[r] = d[rb + k];
    }
    float sh = 0.f, sd = 0.f;
#pragma unroll
    for (int r = 0; r < 8; r++) { sh += hv[r]; sd += dv[r]; }
    sh = warp_sum(sh); sd = warp_sum(sd);
    float m1 = sh * (1.f / 256.f), m2 = sd * (1.f / 256.f);
    float q1 = 0.f, q2 = 0.f;
#pragma unroll
    for (int r = 0; r < 8; r++) {
        float e1 = hv[r] - m1; q1 += e1 * e1;
        float e2 = dv[r] - m2; q2 += e2 * e2;
    }
    q1 = warp_sum(q1); q2 = warp_sum(q2);
    float i1 = rsqrtf(q1 * (1.f / 256.f) + 1e-6f);
    float i2 = rsqrtf(q2 * (1.f / 256.f) + 1e-6f);
#pragma unroll
    for (int r = 0; r < 8; r++) {
        int k = lane + 32 * r;
        float v = g1[k] * (hv[r] - m1) * i1 + b1[k] + g2[k] * (dv[r] - m2) * i2 + b2[k];
        crossbuf[rb + k] = v;
        if (cross_out) cross_out[rb + k] = v;
    }
}

__global__ void __launch_bounds__(256) k_out(
    const float* __restrict__ cross, const float* __restrict__ Wout,
    const float* __restrict__ bout, float* __restrict__ out)
{
    __shared__ float Ws[256 * 41];
    __shared__ float bs[NC];
    int t = threadIdx.x;
    for (int i = t; i < 256 * NC; i += 256) {
        int k = i / NC, c = i - k * NC;
        Ws[k * 41 + c] = Wout[i];
    }
    if (t < NC) bs[t] = bout[t];
    __syncthreads();

    int row = blockIdx.x * 8 + (t >> 5);
    int lane = t & 31;
    if (row >= NN) return;

    float acc[NC];
#pragma unroll
    for (int c = 0; c < NC; c++) acc[c] = 0.f;
    size_t rb = (size_t)row * H;
#pragma unroll
    for (int r = 0; r < 8; r++) {
        int k = lane + 32 * r;
        float v = cross[rb + k];
        const float* wr = &Ws[k * 41];
#pragma unroll
        for (int c = 0; c < NC; c++) acc[c] += v * wr[c];
    }
#pragma unroll
    for (int c = 0; c < NC; c++)
#pragma unroll
        for (int off = 16; off; off >>= 1) acc[c] += __shfl_xor_sync(0xffffffffu, acc[c], off);

    float m = -1e30f;
#pragma unroll
    for (int c = 0; c < NC; c++) { acc[c] += bs[c]; m = fmaxf(m, acc[c]); }
    float s = 0.f;
#pragma unroll
    for (int c = 0; c < NC; c++) s += expf(acc[c] - m);
    float lse = m + logf(s);
    float* o = out + (size_t)row * NC;
#pragma unroll
    for (int c = 0; c < NC; c++)
        if ((c & 31) == lane) o[c] = acc[c] - lse;
}

// ---------------- launch ---------------------------------------------------
extern "C" void kernel_launch(void* const* d_in, const int* in_sizes, int n_in,
                              void* d_out, int out_size)
{
    const float* x     = (const float*)d_in[0];
    const int*   esrc  = (const int*)d_in[1];
    const int*   edst  = (const int*)d_in[2];
    const float* ew    = (const float*)d_in[3];
    const float* Wfc   = (const float*)d_in[4];
    const float* bfc   = (const float*)d_in[5];
    const float* convw = (const float*)d_in[6];
    const float* dynw  = (const float*)d_in[7];
    const float* dynb  = (const float*)d_in[8];
    const float* g1    = (const float*)d_in[9];
    const float* b1    = (const float*)d_in[10];
    const float* g2    = (const float*)d_in[11];
    const float* b2    = (const float*)d_in[12];
    const float* Wout  = (const float*)d_in[13];
    const float* bout  = (const float*)d_in[14];
    float* out = (float*)d_out;

    float *h0f, *hf, *hif, *df, *cpf;
    cudaGetSymbolAddress((void**)&h0f, g_h0f);
    cudaGetSymbolAddress((void**)&hf,  g_hf);
    cudaGetSymbolAddress((void**)&hif, g_hif);
    cudaGetSymbolAddress((void**)&df,  g_df);
    cudaGetSymbolAddress((void**)&cpf, g_cpf);
    __nv_bfloat16 *bxh, *bxl, *bh0h, *bh0l, *bhih, *bhil, *bdAh, *bdAl, *bdBh, *bdBl, *w9h, *w9l, *wdh, *wdl;
    cudaGetSymbolAddress((void**)&bxh, g_bx_hi);
    cudaGetSymbolAddress((void**)&bxl, g_bx_lo);
    cudaGetSymbolAddress((void**)&bh0h, g_bh0_hi);
    cudaGetSymbolAddress((void**)&bh0l, g_bh0_lo);
    cudaGetSymbolAddress((void**)&bhih, g_bhi_hi);
    cudaGetSymbolAddress((void**)&bhil, g_bhi_lo);
    cudaGetSymbolAddress((void**)&bdAh, g_bdA_hi);
    cudaGetSymbolAddress((void**)&bdAl, g_bdA_lo);
    cudaGetSymbolAddress((void**)&bdBh, g_bdB_hi);
    cudaGetSymbolAddress((void**)&bdBl, g_bdB_lo);
    cudaGetSymbolAddress((void**)&w9h, g_wt9_hi);
    cudaGetSymbolAddress((void**)&w9l, g_wt9_lo);
    cudaGetSymbolAddress((void**)&wdh, g_wtd_hi);
    cudaGetSymbolAddress((void**)&wdl, g_wtd_lo);

    cudaFuncSetAttribute(k_gemm_big<0>, cudaFuncAttributeMaxDynamicSharedMemorySize, SMEM_BIG);
    cudaFuncSetAttribute(k_gemm_big<1>, cudaFuncAttributeMaxDynamicSharedMemorySize, SMEM_BIG);
    cudaFuncSetAttribute(k_sd,          cudaFuncAttributeMaxDynamicSharedMemorySize, SMEM_SMALL);

    // prep
    k_convx<<<(NN * 512 + 255) / 256, 256>>>(x);
    k_wprep9<<<(9 * 512 * 256 + 255) / 256, 256>>>(Wfc, convw);
    k_wprepd<<<(NL * 256 * 256 + 255) / 256, 256>>>(dynw);

    // fc: h = h0 = relu(x@Wfc + bfc)
    k_gemm_big<0><<<GRID_M, 256, SMEM_BIG>>>(
        bxh, bxl, 512, 512, w9h, w9l, 512,
        hf, bfc, nullptr, nullptr, nullptr, nullptr, 0.f,
        bh0h, bh0l, h0f);

    // CSR build (independent of fc)
    k_zero<<<(NN + 255) / 256, 256>>>();
    k_hist<<<NE / 256, 256>>>(edst);
    k_scan1<<<98, 256>>>();
    k_scan2<<<1, 128>>>(98);
    k_scan3<<<98, 256>>>();
    k_scatter<<<NE / 256, 256>>>(esrc, edst, ew);

    for (int i = 0; i < NL; i++) {
        const __nv_bfloat16* dinh = (i == 0) ? bh0h : ((i & 1) ? bdAh : bdBh);
        const __nv_bfloat16* dinl = (i == 0) ? bh0l : ((i & 1) ? bdAl : bdBl);
        __nv_bfloat16* douh = (i & 1) ? bdBh : bdAh;
        __nv_bfloat16* doul = (i & 1) ? bdBl : bdAl;
        const __nv_bfloat16* wlh = w9h + (size_t)(1 + i) * 256 * 512;
        const __nv_bfloat16* wll = w9l + (size_t)(1 + i) * 256 * 512;

        // fused: SpMM(h->hi) + dyn GEMM (d->d_next) + conv partial (h0@W_bot->cpf)
        k_sd<<<FUSED_GRID, 256, SMEM_SMALL>>>(
            dinh, dinl, wdh + (size_t)i * 256 * 256, wdl + (size_t)i * 256 * 256,
            df, dynb + (size_t)i * H, h0f, (i > 0) ? 0.1f : 0.f,
            douh, doul,
            bh0h, bh0l, wlh + 256, wll + 256, cpf,
            hf, hif, bhih, bhil);

        float theta = logf(0.5f / (float)(i + 1) + 1.0f);
        // conv post: h = relu(theta*(hi@W_top + cpf) + (1-theta)*(0.9*hi+0.1*h0) + h)
        k_gemm_big<1><<<GRID_M, 256, SMEM_BIG>>>(
            bhih, bhil, 256, 256, wlh, wll, 512,
            hf, nullptr, hif, h0f, hf, cpf, theta,
            nullptr, nullptr, nullptr);
    }

    float* cross_out_ptr = (out_size >= NN * (NC + H)) ? (out + (size_t)NN * NC) : nullptr;
    k_cross<<<NN / 8, 256>>>(hf, df, g1, b1, g2, b2, hif /*scratch*/, cross_out_ptr);
    k_out<<<NN / 8, 256>>>(hif, Wout, bout, out);
}

// round 10
// speedup vs baseline: 1.0305x; 1.0305x over previous
#include <cuda_runtime.h>
#include <cuda_bf16.h>
#include <math.h>
#include <stdint.h>

#define NN 100000
#define NE 3200000
#define H  256
#define NC 40
#define NL 8
#define MPAD 100096          // 782 * 128
#define GRID_M 782

// ---------------- device scratch (no allocations allowed) ------------------
__device__ int   g_deg[NN];
__device__ int   g_cur[NN];
__device__ int   g_rowptr[NN + 1];
__device__ int   g_bsums[128];
__device__ int   g_csrc[NE];
__device__ float g_cw[NE];

__device__ float g_h0f[MPAD * H];
__device__ float g_hf [MPAD * H];
__device__ float g_hif[MPAD * H];
__device__ float g_df [MPAD * H];
__device__ float g_cpf[MPAD * H];     // conv partial: h0 @ W_bot

__device__ __nv_bfloat16 g_bx_hi[MPAD * 512];
__device__ __nv_bfloat16 g_bx_lo[MPAD * 512];
__device__ __nv_bfloat16 g_bh0_hi[MPAD * H];
__device__ __nv_bfloat16 g_bh0_lo[MPAD * H];
__device__ __nv_bfloat16 g_bhi_hi[MPAD * H];
__device__ __nv_bfloat16 g_bhi_lo[MPAD * H];
__device__ __nv_bfloat16 g_bdA_hi[MPAD * H];
__device__ __nv_bfloat16 g_bdA_lo[MPAD * H];
__device__ __nv_bfloat16 g_bdB_hi[MPAD * H];
__device__ __nv_bfloat16 g_bdB_lo[MPAD * H];

// weights, pre-transposed to [N=256][K] row-major, bf16 split
__device__ __nv_bfloat16 g_wt9_hi[9 * H * 512];   // fc + 8 conv (K=512)
__device__ __nv_bfloat16 g_wt9_lo[9 * H * 512];
__device__ __nv_bfloat16 g_wtd_hi[NL * H * H];    // dyn effective (K=256)
__device__ __nv_bfloat16 g_wtd_lo[NL * H * H];

// ---------------- helpers --------------------------------------------------
__device__ __forceinline__ uint32_t smem_u32(const void* p) {
    uint32_t a;
    asm("{ .reg .u64 t; cvta.to.shared.u64 t, %1; cvt.u32.u64 %0, t; }" : "=r"(a) : "l"(p));
    return a;
}
#define SW128(o) ((o) ^ (((o) >> 3) & 0x70))

__device__ __forceinline__ void cpasync16(uint32_t dst, const void* src, int srcsize) {
    uint64_t g = __cvta_generic_to_global(src);
    asm volatile("cp.async.cg.shared.global [%0], [%1], 16, %2;"
                 :: "r"(dst), "l"(g), "r"(srcsize) : "memory");
}
#define CP_COMMIT() asm volatile("cp.async.commit_group;" ::: "memory")
#define CP_WAIT0()  asm volatile("cp.async.wait_group 0;" ::: "memory")

__device__ __forceinline__ void ldx4(uint32_t* r, uint32_t addr) {
    asm volatile("ldmatrix.sync.aligned.m8n8.x4.shared.b16 {%0,%1,%2,%3}, [%4];"
                 : "=r"(r[0]), "=r"(r[1]), "=r"(r[2]), "=r"(r[3]) : "r"(addr));
}
__device__ __forceinline__ void ldx2(uint32_t* r, uint32_t addr) {
    asm volatile("ldmatrix.sync.aligned.m8n8.x2.shared.b16 {%0,%1}, [%2];"
                 : "=r"(r[0]), "=r"(r[1]) : "r"(addr));
}
__device__ __forceinline__ void mma16816(float* c, const uint32_t* a, const uint32_t* b) {
    asm volatile("mma.sync.aligned.m16n8k16.row.col.f32.bf16.bf16.f32 "
                 "{%0,%1,%2,%3}, {%4,%5,%6,%7}, {%8,%9}, {%0,%1,%2,%3};"
                 : "+f"(c[0]), "+f"(c[1]), "+f"(c[2]), "+f"(c[3])
                 : "r"(a[0]), "r"(a[1]), "r"(a[2]), "r"(a[3]), "r"(b[0]), "r"(b[1]));
}

// smem: single 64KB buffer: [Ahi 16K][Alo 16K][Bhi 16K][Blo 16K]
#define SMEM_TOTAL 65536

// ---------------- CSR build ------------------------------------------------
__global__ void k_zero() {
    int i = blockIdx.x * blockDim.x + threadIdx.x;
    if (i < NN) { g_deg[i] = 0; g_cur[i] = 0; }
}
__global__ void k_hist(const int* __restrict__ dst) {
    int e = blockIdx.x * blockDim.x + threadIdx.x;
    if (e < NE) atomicAdd(&g_deg[dst[e]], 1);
}
__global__ void k_scan1() {
    __shared__ int sh[256];
    int b = blockIdx.x, t = threadIdx.x;
    int base = b * 1024 + t * 4;
    int v[4], loc[4];
#pragma unroll
    for (int j = 0; j < 4; j++) { int idx = base + j; v[j] = (idx < NN) ? g_deg[idx] : 0; }
    loc[0] = v[0];
#pragma unroll
    for (int j = 1; j < 4; j++) loc[j] = loc[j - 1] + v[j];
    sh[t] = loc[3];
    __syncthreads();
    for (int off = 1; off < 256; off <<= 1) {
        int x = (t >= off) ? sh[t - off] : 0;
        __syncthreads();
        sh[t] += x;
        __syncthreads();
    }
    int pre = (t > 0) ? sh[t - 1] : 0;
#pragma unroll
    for (int j = 0; j < 4; j++) { int idx = base + j; if (idx < NN) g_rowptr[idx + 1] = pre + loc[j]; }
    if (t == 255) g_bsums[b] = sh[255];
}
__global__ void k_scan2(int nb) {
    __shared__ int sh[128];
    int t = threadIdx.x;
    sh[t] = (t < nb) ? g_bsums[t] : 0;
    __syncthreads();
    for (int off = 1; off < 128; off <<= 1) {
        int x = (t >= off) ? sh[t - off] : 0;
        __syncthreads();
        sh[t] += x;
        __syncthreads();
    }
    g_bsums[t] = sh[t];
}
__global__ void k_scan3() {
    int b = blockIdx.x, t = threadIdx.x;
    int add = (b > 0) ? g_bsums[b - 1] : 0;
#pragma unroll
    for (int j = 0; j < 4; j++) {
        int idx = b * 1024 + t * 4 + j;
        if (idx < NN) g_rowptr[idx + 1] += add;
    }
    if (b == 0 && t == 0) g_rowptr[0] = 0;
}
__global__ void k_scatter(const int* __restrict__ src, const int* __restrict__ dst,
                          const float* __restrict__ w) {
    int e = blockIdx.x * blockDim.x + threadIdx.x;
    if (e < NE) {
        int d = dst[e];
        int pos = g_rowptr[d] + atomicAdd(&g_cur[d], 1);
        g_csrc[pos] = src[e];
        g_cw[pos] = w[e];
    }
}

// ---------------- weight prep (transpose + bf16 split) ---------------------
__device__ __forceinline__ void bsplit(float v, __nv_bfloat16& hi, __nv_bfloat16& lo) {
    hi = __float2bfloat16_rn(v);
    lo = __float2bfloat16_rn(v - __bfloat162float(hi));
}
__global__ void k_wprep9(const float* __restrict__ Wfc, const float* __restrict__ convw) {
    int idx = blockIdx.x * blockDim.x + threadIdx.x;
    if (idx >= 9 * 512 * 256) return;
    int m = idx / (512 * 256);
    int r = idx - m * 512 * 256;
    int k = r / 256, n = r - k * 256;
    float v = (m == 0) ? Wfc[r] : convw[(m - 1) * 512 * 256 + r];
    __nv_bfloat16 hi, lo; bsplit(v, hi, lo);
    size_t o = (size_t)m * 256 * 512 + (size_t)n * 512 + k;
    g_wt9_hi[o] = hi; g_wt9_lo[o] = lo;
}
__global__ void k_wprepd(const float* __restrict__ dynw) {
    int idx = blockIdx.x * blockDim.x + threadIdx.x;
    if (idx >= NL * 256 * 256) return;
    int i = idx / (256 * 256);
    int r = idx - i * 256 * 256;
    int k = r / 256, n = r - k * 256;
    const float* base = dynw + (size_t)i * 512 * 256;
    float v = base[k * 256 + n] - base[(k + 256) * 256 + n];
    __nv_bfloat16 hi, lo; bsplit(v, hi, lo);
    size_t o = (size_t)i * 256 * 256 + (size_t)n * 256 + k;
    g_wtd_hi[o] = hi; g_wtd_lo[o] = lo;
}
__global__ void k_convx(const float* __restrict__ x) {
    int idx = blockIdx.x * blockDim.x + threadIdx.x;
    if (idx >= NN * 512) return;
    __nv_bfloat16 hi, lo; bsplit(x[idx], hi, lo);
    g_bx_hi[idx] = hi; g_bx_lo[idx] = lo;
}

// ============ small-tile GEMM block (R6-proven config) ======================
// C[128 x 128-slice] = A[M,K] @ W^T, bf16 split, fp32 acc, regs ~128, 2 CTA/SM
// MODE 0 fc      : v=relu(acc+bias); write C(hf), C2(h0f), Chi/Clo(bh0)
// MODE 1 conv    : v=relu(theta*(acc+Cpart)+(1-theta)*(0.9*Ehi+0.1*Eh0)+Eh)
// MODE 2 dyn     : v=relu(acc+bias)+res*Eh0; write C(df), Chi/Clo
// MODE 3 convpart: C = acc (f32)
template <int MODE>
__device__ void gemm_block(
           int bx, int by,
           const __nv_bfloat16* __restrict__ Ah_, const __nv_bfloat16* __restrict__ Al_, int sA,
           int K,
           const __nv_bfloat16* __restrict__ Bh, const __nv_bfloat16* __restrict__ Bl, int Bst,
           float* __restrict__ C, const float* __restrict__ bias,
           const float* __restrict__ Ehi, const float* __restrict__ Eh0, const float* __restrict__ Eh,
           const float* __restrict__ Cpart, float theta, float res_scale,
           __nv_bfloat16* __restrict__ Chi, __nv_bfloat16* __restrict__ Clo,
           float* __restrict__ C2)
{
    extern __shared__ char smc[];
    uint32_t sb = smem_u32(smc);
    int t = threadIdx.x, lane = t & 31, wid = t >> 5;
    int widm = wid >> 2, widn = wid & 3;   // 2 x 4 warp grid
    int bn0 = bx * 128;
    int bm0 = by * 128;

    float acc[4][4][4];
#pragma unroll
    for (int a = 0; a < 4; a++)
#pragma unroll
        for (int b = 0; b < 4; b++)
#pragma unroll
            for (int c = 0; c < 4; c++) acc[a][b][c] = 0.f;

    const int nc = K / 64;

    int mi = lane >> 3;
    int arow_off = (lane & 7) + ((mi & 1) << 3);
    int akcol = (mi >> 1) << 4;
    int brow_off = (lane & 7);
    int bkcol = ((lane >> 3) & 1) << 4;

    for (int c = 0; c < nc; c++) {
        {
            int kk0 = c * 64;
#pragma unroll
            for (int j = 0; j < 4; j++) {
                int idx = t + j * 256;
                int r = idx >> 3, c16 = idx & 7;
                uint32_t d = SW128(r * 128 + c16 * 16);
                int grow = bm0 + r;
                int kk = kk0 + c16 * 8;
                int pred = 16;
                if (grow >= NN) { grow = 0; pred = 0; }
                cpasync16(sb + d,         Ah_ + (size_t)grow * sA + kk, pred);
                cpasync16(sb + 16384 + d, Al_ + (size_t)grow * sA + kk, pred);
                size_t bo = (size_t)(bn0 + r) * Bst + kk0 + c16 * 8;
                cpasync16(sb + 32768 + d, Bh + bo, 16);
                cpasync16(sb + 49152 + d, Bl + bo, 16);
            }
            CP_COMMIT();
        }
        CP_WAIT0();
        __syncthreads();
#pragma unroll
        for (int ks = 0; ks < 4; ks++) {
            int kb = ks * 32;
            uint32_t Bh2[4][2], Bl2[4][2];
#pragma unroll
            for (int nt = 0; nt < 4; nt++) {
                int row = widn * 32 + nt * 8 + brow_off;
                uint32_t bd = sb + 32768 + SW128(row * 128 + kb + bkcol);
                ldx2(Bh2[nt], bd);
                ldx2(Bl2[nt], bd + 16384);
            }
#pragma unroll
            for (int mt = 0; mt < 4; mt++) {
                uint32_t Ah[4], Al[4];
                int row = widm * 64 + mt * 16 + arow_off;
                uint32_t ad = sb + SW128(row * 128 + kb + akcol);
                ldx4(Ah, ad);
                ldx4(Al, ad + 16384);
#pragma unroll
                for (int nt = 0; nt < 4; nt++) {
                    mma16816(acc[mt][nt], Ah, Bh2[nt]);
                    mma16816(acc[mt][nt], Ah, Bl2[nt]);
                    mma16816(acc[mt][nt], Al, Bh2[nt]);
                }
            }
        }
        __syncthreads();
    }

    // ---- epilogue ----
#pragma unroll
    for (int mt = 0; mt < 4; mt++) {
#pragma unroll
        for (int nt = 0; nt < 4; nt++) {
            int cb = bn0 + widn * 32 + nt * 8 + (lane & 3) * 2;
#pragma unroll
            for (int half = 0; half < 2; half++) {
                int row = bm0 + widm * 64 + mt * 16 + (lane >> 2) + half * 8;
                if (row >= NN) continue;
                size_t rb = (size_t)row * H + cb;
                float v0 = acc[mt][nt][half * 2 + 0];
                float v1 = acc[mt][nt][half * 2 + 1];
                if (MODE == 0) {
                    v0 = fmaxf(v0 + bias[cb], 0.f);
                    v1 = fmaxf(v1 + bias[cb + 1], 0.f);
                } else if (MODE == 1) {
                    float2 cp = *(const float2*)(Cpart + rb);
                    float2 e1 = *(const float2*)(Ehi + rb);
                    float2 e2 = *(const float2*)(Eh0 + rb);
                    float2 e3 = *(const float2*)(Eh + rb);
                    v0 = fmaxf(theta * (v0 + cp.x) + (1.f - theta) * (0.9f * e1.x + 0.1f * e2.x) + e3.x, 0.f);
                    v1 = fmaxf(theta * (v1 + cp.y) + (1.f - theta) * (0.9f * e1.y + 0.1f * e2.y) + e3.y, 0.f);
                } else if (MODE == 2) {
                    float2 e2 = *(const float2*)(Eh0 + rb);
                    v0 = fmaxf(v0 + bias[cb], 0.f) + res_scale * e2.x;
                    v1 = fmaxf(v1 + bias[cb + 1], 0.f) + res_scale * e2.y;
                }
                *(float2*)(C + rb) = make_float2(v0, v1);
                if (MODE == 0) *(float2*)(C2 + rb) = make_float2(v0, v1);
                if (MODE == 0 || MODE == 2) {
                    union { uint32_t u; __nv_bfloat16 b[2]; } ph_, pl_;
                    __nv_bfloat16 h0b = __float2bfloat16_rn(v0);
                    __nv_bfloat16 h1b = __float2bfloat16_rn(v1);
                    ph_.b[0] = h0b; ph_.b[1] = h1b;
                    pl_.b[0] = __float2bfloat16_rn(v0 - __bfloat162float(h0b));
                    pl_.b[1] = __float2bfloat16_rn(v1 - __bfloat162float(h1b));
                    *(uint32_t*)(Chi + rb) = ph_.u;
                    *(uint32_t*)(Clo + rb) = pl_.u;
                }
            }
        }
    }
}

template <int MODE>
__global__ void __launch_bounds__(256, 2)
k_gemm(const __nv_bfloat16* Ah_, const __nv_bfloat16* Al_, int sA, int K,
       const __nv_bfloat16* Bh, const __nv_bfloat16* Bl, int Bst,
       float* C, const float* bias,
       const float* Ehi, const float* Eh0, const float* Eh,
       const float* Cpart, float theta, float res_scale,
       __nv_bfloat16* Chi, __nv_bfloat16* Clo, float* C2)
{
    gemm_block<MODE>(blockIdx.x, blockIdx.y, Ah_, Al_, sA, K, Bh, Bl, Bst,
                     C, bias, Ehi, Eh0, Eh, Cpart, theta, res_scale, Chi, Clo, C2);
}

// ---------------- SpMM block (device function) ------------------------------
__device__ void spmm_block(int node_base, const float* __restrict__ h,
                           float* __restrict__ hif,
                           __nv_bfloat16* __restrict__ bhih,
                           __nv_bfloat16* __restrict__ bhil) {
    int wid = threadIdx.x >> 5, lane = threadIdx.x & 31;
    int node = node_base + wid;
    if (node >= NN) return;
    int s0 = g_rowptr[node], s1 = g_rowptr[node + 1];
    float4 a0 = make_float4(0.f, 0.f, 0.f, 0.f);
    float4 a1 = make_float4(0.f, 0.f, 0.f, 0.f);
    const float4* h4 = (const float4*)h;
    int e = s0;
    for (; e + 3 < s1; e += 4) {
        int si[4]; float w[4];
#pragma unroll
        for (int u = 0; u < 4; u++) { si[u] = g_csrc[e + u]; w[u] = g_cw[e + u]; }
        float4 v0[4], v1[4];
#pragma unroll
        for (int u = 0; u < 4; u++) {
            const float4* p = h4 + (size_t)si[u] * 64;
            v0[u] = __ldg(p + lane);
            v1[u] = __ldg(p + lane + 32);
        }
#pragma unroll
        for (int u = 0; u < 4; u++) {
            a0.x += w[u] * v0[u].x; a0.y += w[u] * v0[u].y;
            a0.z += w[u] * v0[u].z; a0.w += w[u] * v0[u].w;
            a1.x += w[u] * v1[u].x; a1.y += w[u] * v1[u].y;
            a1.z += w[u] * v1[u].z; a1.w += w[u] * v1[u].w;
        }
    }
    for (; e < s1; e++) {
        int sA = g_csrc[e];
        float wA = g_cw[e];
        const float4* pA = h4 + (size_t)sA * 64;
        float4 vA0 = __ldg(pA + lane), vA1 = __ldg(pA + lane + 32);
        a0.x += wA * vA0.x; a0.y += wA * vA0.y; a0.z += wA * vA0.z; a0.w += wA * vA0.w;
        a1.x += wA * vA1.x; a1.y += wA * vA1.y; a1.z += wA * vA1.z; a1.w += wA * vA1.w;
    }
    float4* op = (float4*)hif + (size_t)node * 64;
    op[lane] = a0;
    op[lane + 32] = a1;
    size_t rb = (size_t)node * H;
    union { uint2 u; __nv_bfloat16 b[4]; } ph_, pl_;
    float va[4] = {a0.x, a0.y, a0.z, a0.w};
#pragma unroll
    for (int i = 0; i < 4; i++) {
        __nv_bfloat16 hb = __float2bfloat16_rn(va[i]);
        ph_.b[i] = hb; pl_.b[i] = __float2bfloat16_rn(va[i] - __bfloat162float(hb));
    }
    *(uint2*)(bhih + rb + lane * 4) = ph_.u;
    *(uint2*)(bhil + rb + lane * 4) = pl_.u;
    float vb[4] = {a1.x, a1.y, a1.z, a1.w};
#pragma unroll
    for (int i = 0; i < 4; i++) {
        __nv_bfloat16 hb = __float2bfloat16_rn(vb[i]);
        ph_.b[i] = hb; pl_.b[i] = __float2bfloat16_rn(vb[i] - __bfloat162float(hb));
    }
    *(uint2*)(bhih + rb + 128 + lane * 4) = ph_.u;
    *(uint2*)(bhil + rb + 128 + lane * 4) = pl_.u;
}

// ---------------- fused SpMM + dyn-GEMM + conv-partial ----------------------
// gemm ids: even -> dyn (MODE 2), odd -> convpart (MODE 3); every 5th block.
#define FUSED_GRID 15640
__global__ void __launch_bounds__(256, 2)
k_sd(const __nv_bfloat16* dinh, const __nv_bfloat16* dinl,
     const __nv_bfloat16* wdh, const __nv_bfloat16* wdl,
     float* df, const float* dynb, const float* h0f, float res_scale,
     __nv_bfloat16* douh, __nv_bfloat16* doul,
     const __nv_bfloat16* bh0h, const __nv_bfloat16* bh0l,
     const __nv_bfloat16* cwbh, const __nv_bfloat16* cwbl, float* cpf,
     const float* hf, float* hif, __nv_bfloat16* bhih, __nv_bfloat16* bhil)
{
    int bid = blockIdx.x;
    if (bid % 5 == 0) {
        int g = bid / 5;
        if (g < 3128) {
            int sub = g >> 1;
            int bx = sub & 1, by = sub >> 1;
            if ((g & 1) == 0)
                gemm_block<2>(bx, by, dinh, dinl, 256, 256, wdh, wdl, 256,
                              df, dynb, nullptr, h0f, nullptr, nullptr, 0.f, res_scale,
                              douh, doul, nullptr);
            else
                gemm_block<3>(bx, by, bh0h, bh0l, 256, 256, cwbh, cwbl, 512,
                              cpf, nullptr, nullptr, nullptr, nullptr, nullptr, 0.f, 0.f,
                              nullptr, nullptr, nullptr);
        }
    } else {
        int sid = bid - bid / 5 - 1;
        if (sid < NN / 8)
            spmm_block(sid * 8, hf, hif, bhih, bhil);
    }
}

// ---------------- LN cross + output ----------------------------------------
__device__ __forceinline__ float warp_sum(float v) {
#pragma unroll
    for (int off = 16; off; off >>= 1) v += __shfl_xor_sync(0xffffffffu, v, off);
    return v;
}

__global__ void __launch_bounds__(256) k_cross(
    const float* __restrict__ h, const float* __restrict__ d,
    const float* __restrict__ g1, const float* __restrict__ b1,
    const float* __restrict__ g2, const float* __restrict__ b2,
    float* __restrict__ crossbuf, float* __restrict__ cross_out)
{
    int row = blockIdx.x * 8 + (threadIdx.x >> 5);
    int lane = threadIdx.x & 31;
    if (row >= NN) return;
    size_t rb = (size_t)row * H;
    float hv[8], dv[8];
#pragma unroll
    for (int r = 0; r < 8; r++) {
        int k = lane + 32 * r;
        hv[r] = h[rb + k];
        dv[r] = d[rb + k];
    }
    float sh = 0.f, sd = 0.f;
#pragma unroll
    for (int r = 0; r < 8; r++) { sh += hv[r]; sd += dv[r]; }
    sh = warp_sum(sh); sd = warp_sum(sd);
    float m1 = sh * (1.f / 256.f), m2 = sd * (1.f / 256.f);
    float q1 = 0.f, q2 = 0.f;
#pragma unroll
    for (int r = 0; r < 8; r++) {
        float e1 = hv[r] - m1; q1 += e1 * e1;
        float e2 = dv[r] - m2; q2 += e2 * e2;
    }
    q1 = warp_sum(q1); q2 = warp_sum(q2);
    float i1 = rsqrtf(q1 * (1.f / 256.f) + 1e-6f);
    float i2 = rsqrtf(q2 * (1.f / 256.f) + 1e-6f);
#pragma unroll
    for (int r = 0; r < 8; r++) {
        int k = lane + 32 * r;
        float v = g1[k] * (hv[r] - m1) * i1 + b1[k] + g2[k] * (dv[r] - m2) * i2 + b2[k];
        crossbuf[rb + k] = v;
        if (cross_out) cross_out[rb + k] = v;
    }
}

__global__ void __launch_bounds__(256) k_out(
    const float* __restrict__ cross, const float* __restrict__ Wout,
    const float* __restrict__ bout, float* __restrict__ out)
{
    __shared__ float Ws[256 * 41];
    __shared__ float bs[NC];
    int t = threadIdx.x;
    for (int i = t; i < 256 * NC; i += 256) {
        int k = i / NC, c = i - k * NC;
        Ws[k * 41 + c] = Wout[i];
    }
    if (t < NC) bs[t] = bout[t];
    __syncthreads();

    int row = blockIdx.x * 8 + (t >> 5);
    int lane = t & 31;
    if (row >= NN) return;

    float acc[NC];
#pragma unroll
    for (int c = 0; c < NC; c++) acc[c] = 0.f;
    size_t rb = (size_t)row * H;
#pragma unroll
    for (int r = 0; r < 8; r++) {
        int k = lane + 32 * r;
        float v = cross[rb + k];
        const float* wr = &Ws[k * 41];
#pragma unroll
        for (int c = 0; c < NC; c++) acc[c] += v * wr[c];
    }
#pragma unroll
    for (int c = 0; c < NC; c++)
#pragma unroll
        for (int off = 16; off; off >>= 1) acc[c] += __shfl_xor_sync(0xffffffffu, acc[c], off);

    float m = -1e30f;
#pragma unroll
    for (int c = 0; c < NC; c++) { acc[c] += bs[c]; m = fmaxf(m, acc[c]); }
    float s = 0.f;
#pragma unroll
    for (int c = 0; c < NC; c++) s += expf(acc[c] - m);
    float lse = m + logf(s);
    float* o = out + (size_t)row * NC;
#pragma unroll
    for (int c = 0; c < NC; c++)
        if ((c & 31) == lane) o[c] = acc[c] - lse;
}

// ---------------- launch ---------------------------------------------------
extern "C" void kernel_launch(void* const* d_in, const int* in_sizes, int n_in,
                              void* d_out, int out_size)
{
    const float* x     = (const float*)d_in[0];
    const int*   esrc  = (const int*)d_in[1];
    const int*   edst  = (const int*)d_in[2];
    const float* ew    = (const float*)d_in[3];
    const float* Wfc   = (const float*)d_in[4];
    const float* bfc   = (const float*)d_in[5];
    const float* convw = (const float*)d_in[6];
    const float* dynw  = (const float*)d_in[7];
    const float* dynb  = (const float*)d_in[8];
    const float* g1    = (const float*)d_in[9];
    const float* b1    = (const float*)d_in[10];
    const float* g2    = (const float*)d_in[11];
    const float* b2    = (const float*)d_in[12];
    const float* Wout  = (const float*)d_in[13];
    const float* bout  = (const float*)d_in[14];
    float* out = (float*)d_out;

    float *h0f, *hf, *hif, *df, *cpf;
    cudaGetSymbolAddress((void**)&h0f, g_h0f);
    cudaGetSymbolAddress((void**)&hf,  g_hf);
    cudaGetSymbolAddress((void**)&hif, g_hif);
    cudaGetSymbolAddress((void**)&df,  g_df);
    cudaGetSymbolAddress((void**)&cpf, g_cpf);
    __nv_bfloat16 *bxh, *bxl, *bh0h, *bh0l, *bhih, *bhil, *bdAh, *bdAl, *bdBh, *bdBl, *w9h, *w9l, *wdh, *wdl;
    cudaGetSymbolAddress((void**)&bxh, g_bx_hi);
    cudaGetSymbolAddress((void**)&bxl, g_bx_lo);
    cudaGetSymbolAddress((void**)&bh0h, g_bh0_hi);
    cudaGetSymbolAddress((void**)&bh0l, g_bh0_lo);
    cudaGetSymbolAddress((void**)&bhih, g_bhi_hi);
    cudaGetSymbolAddress((void**)&bhil, g_bhi_lo);
    cudaGetSymbolAddress((void**)&bdAh, g_bdA_hi);
    cudaGetSymbolAddress((void**)&bdAl, g_bdA_lo);
    cudaGetSymbolAddress((void**)&bdBh, g_bdB_hi);
    cudaGetSymbolAddress((void**)&bdBl, g_bdB_lo);
    cudaGetSymbolAddress((void**)&w9h, g_wt9_hi);
    cudaGetSymbolAddress((void**)&w9l, g_wt9_lo);
    cudaGetSymbolAddress((void**)&wdh, g_wtd_hi);
    cudaGetSymbolAddress((void**)&wdl, g_wtd_lo);

    cudaFuncSetAttribute(k_gemm<0>, cudaFuncAttributeMaxDynamicSharedMemorySize, SMEM_TOTAL);
    cudaFuncSetAttribute(k_gemm<1>, cudaFuncAttributeMaxDynamicSharedMemorySize, SMEM_TOTAL);
    cudaFuncSetAttribute(k_sd,      cudaFuncAttributeMaxDynamicSharedMemorySize, SMEM_TOTAL);

    dim3 grid(2, GRID_M);

    // prep
    k_convx<<<(NN * 512 + 255) / 256, 256>>>(x);
    k_wprep9<<<(9 * 512 * 256 + 255) / 256, 256>>>(Wfc, convw);
    k_wprepd<<<(NL * 256 * 256 + 255) / 256, 256>>>(dynw);

    // fc: h = h0 = relu(x@Wfc + bfc)
    k_gemm<0><<<grid, 256, SMEM_TOTAL>>>(
        bxh, bxl, 512, 512, w9h, w9l, 512,
        hf, bfc, nullptr, nullptr, nullptr, nullptr, 0.f, 0.f,
        bh0h, bh0l, h0f);

    // CSR build (independent of fc)
    k_zero<<<(NN + 255) / 256, 256>>>();
    k_hist<<<NE / 256, 256>>>(edst);
    k_scan1<<<98, 256>>>();
    k_scan2<<<1, 128>>>(98);
    k_scan3<<<98, 256>>>();
    k_scatter<<<NE / 256, 256>>>(esrc, edst, ew);

    for (int i = 0; i < NL; i++) {
        const __nv_bfloat16* dinh = (i == 0) ? bh0h : ((i & 1) ? bdAh : bdBh);
        const __nv_bfloat16* dinl = (i == 0) ? bh0l : ((i & 1) ? bdAl : bdBl);
        __nv_bfloat16* douh = (i & 1) ? bdBh : bdAh;
        __nv_bfloat16* doul = (i & 1) ? bdBl : bdAl;
        const __nv_bfloat16* wlh = w9h + (size_t)(1 + i) * 256 * 512;
        const __nv_bfloat16* wll = w9l + (size_t)(1 + i) * 256 * 512;

        // fused: SpMM(h->hi) + dyn GEMM (d->d_next) + conv partial (h0@W_bot->cpf)
        k_sd<<<FUSED_GRID, 256, SMEM_TOTAL>>>(
            dinh, dinl, wdh + (size_t)i * 256 * 256, wdl + (size_t)i * 256 * 256,
            df, dynb + (size_t)i * H, h0f, (i > 0) ? 0.1f : 0.f,
            douh, doul,
            bh0h, bh0l, wlh + 256, wll + 256, cpf,
            hf, hif, bhih, bhil);

        float theta = logf(0.5f / (float)(i + 1) + 1.0f);
        // conv post (K=256): h = relu(theta*(hi@W_top + cpf) + (1-theta)*(0.9*hi+0.1*h0) + h)
        k_gemm<1><<<grid, 256, SMEM_TOTAL>>>(
            bhih, bhil, 256, 256, wlh, wll, 512,
            hf, nullptr, hif, h0f, hf, cpf, theta, 0.f,
            nullptr, nullptr, nullptr);
    }

    float* cross_out_ptr = (out_size >= NN * (NC + H)) ? (out + (size_t)NN * NC) : nullptr;
    k_cross<<<NN / 8, 256>>>(hf, df, g1, b1, g2, b2, hif /*scratch*/, cross_out_ptr);
    k_out<<<NN / 8, 256>>>(hif, Wout, bout, out);
}

// round 12
// speedup vs baseline: 1.0490x; 1.0179x over previous
#include <cuda_runtime.h>
#include <cuda_bf16.h>
#include <math.h>
#include <stdint.h>

#define NN 100000
#define NE 3200000
#define H  256
#define NC 40
#define NL 8
#define MPAD 100096          // 782 * 128
#define GRID_M 782

// ---------------- device scratch (no allocations allowed) ------------------
__device__ int   g_deg[NN];
__device__ int   g_cur[NN];
__device__ int   g_rowptr[NN + 1];
__device__ int   g_bsums[128];
__device__ int   g_csrc[NE];
__device__ float g_cw[NE];

__device__ float g_h0f[MPAD * H];
__device__ float g_hf [MPAD * H];
__device__ float g_hif[MPAD * H];
__device__ float g_df [MPAD * H];

__device__ __nv_bfloat16 g_bx_hi[MPAD * 512];
__device__ __nv_bfloat16 g_bx_lo[MPAD * 512];
__device__ __nv_bfloat16 g_bh0_hi[MPAD * H];
__device__ __nv_bfloat16 g_bh0_lo[MPAD * H];
__device__ __nv_bfloat16 g_bhi_hi[MPAD * H];
__device__ __nv_bfloat16 g_bhi_lo[MPAD * H];
__device__ __nv_bfloat16 g_bdA_hi[MPAD * H];
__device__ __nv_bfloat16 g_bdA_lo[MPAD * H];
__device__ __nv_bfloat16 g_bdB_hi[MPAD * H];
__device__ __nv_bfloat16 g_bdB_lo[MPAD * H];

// weights, pre-transposed to [N=256][K] row-major, bf16 split
__device__ __nv_bfloat16 g_wt9_hi[9 * H * 512];   // fc + 8 conv (K=512)
__device__ __nv_bfloat16 g_wt9_lo[9 * H * 512];
__device__ __nv_bfloat16 g_wtd_hi[NL * H * H];    // dyn effective (K=256)
__device__ __nv_bfloat16 g_wtd_lo[NL * H * H];

// ---------------- helpers --------------------------------------------------
__device__ __forceinline__ uint32_t smem_u32(const void* p) {
    uint32_t a;
    asm("{ .reg .u64 t; cvta.to.shared.u64 t, %1; cvt.u32.u64 %0, t; }" : "=r"(a) : "l"(p));
    return a;
}
#define SW64(o) ((o) ^ (((o) >> 3) & 0x30))

__device__ __forceinline__ void cpasync16(uint32_t dst, const void* src, int srcsize) {
    uint64_t g = __cvta_generic_to_global(src);
    asm volatile("cp.async.cg.shared.global [%0], [%1], 16, %2;"
                 :: "r"(dst), "l"(g), "r"(srcsize) : "memory");
}
#define CP_COMMIT() asm volatile("cp.async.commit_group;" ::: "memory")
#define CP_WAIT1()  asm volatile("cp.async.wait_group 1;" ::: "memory")
#define CP_WAIT0()  asm volatile("cp.async.wait_group 0;" ::: "memory")

__device__ __forceinline__ void ldx4(uint32_t* r, uint32_t addr) {
    asm volatile("ldmatrix.sync.aligned.m8n8.x4.shared.b16 {%0,%1,%2,%3}, [%4];"
                 : "=r"(r[0]), "=r"(r[1]), "=r"(r[2]), "=r"(r[3]) : "r"(addr));
}
__device__ __forceinline__ void ldx2(uint32_t* r, uint32_t addr) {
    asm volatile("ldmatrix.sync.aligned.m8n8.x2.shared.b16 {%0,%1}, [%2];"
                 : "=r"(r[0]), "=r"(r[1]) : "r"(addr));
}
__device__ __forceinline__ void mma16816(float* c, const uint32_t* a, const uint32_t* b) {
    asm volatile("mma.sync.aligned.m16n8k16.row.col.f32.bf16.bf16.f32 "
                 "{%0,%1,%2,%3}, {%4,%5,%6,%7}, {%8,%9}, {%0,%1,%2,%3};"
                 : "+f"(c[0]), "+f"(c[1]), "+f"(c[2]), "+f"(c[3])
                 : "r"(a[0]), "r"(a[1]), "r"(a[2]), "r"(a[3]), "r"(b[0]), "r"(b[1]));
}

// smem: TWO 32KB buffers (BK=32): per buffer [Ahi 8K][Alo 8K][Bhi 8K][Blo 8K]
#define BUFSZ 32768
#define SMEM_TOTAL 65536

// ---------------- CSR build ------------------------------------------------
__global__ void k_zero() {
    int i = blockIdx.x * blockDim.x + threadIdx.x;
    if (i < NN) { g_deg[i] = 0; g_cur[i] = 0; }
}
__global__ void k_hist(const int* __restrict__ dst) {
    int e = blockIdx.x * blockDim.x + threadIdx.x;
    if (e < NE) atomicAdd(&g_deg[dst[e]], 1);
}
__global__ void k_scan1() {
    __shared__ int sh[256];
    int b = blockIdx.x, t = threadIdx.x;
    int base = b * 1024 + t * 4;
    int v[4], loc[4];
#pragma unroll
    for (int j = 0; j < 4; j++) { int idx = base + j; v[j] = (idx < NN) ? g_deg[idx] : 0; }
    loc[0] = v[0];
#pragma unroll
    for (int j = 1; j < 4; j++) loc[j] = loc[j - 1] + v[j];
    sh[t] = loc[3];
    __syncthreads();
    for (int off = 1; off < 256; off <<= 1) {
        int x = (t >= off) ? sh[t - off] : 0;
        __syncthreads();
        sh[t] += x;
        __syncthreads();
    }
    int pre = (t > 0) ? sh[t - 1] : 0;
#pragma unroll
    for (int j = 0; j < 4; j++) { int idx = base + j; if (idx < NN) g_rowptr[idx + 1] = pre + loc[j]; }
    if (t == 255) g_bsums[b] = sh[255];
}
__global__ void k_scan2(int nb) {
    __shared__ int sh[128];
    int t = threadIdx.x;
    sh[t] = (t < nb) ? g_bsums[t] : 0;
    __syncthreads();
    for (int off = 1; off < 128; off <<= 1) {
        int x = (t >= off) ? sh[t - off] : 0;
        __syncthreads();
        sh[t] += x;
        __syncthreads();
    }
    g_bsums[t] = sh[t];
}
__global__ void k_scan3() {
    int b = blockIdx.x, t = threadIdx.x;
    int add = (b > 0) ? g_bsums[b - 1] : 0;
#pragma unroll
    for (int j = 0; j < 4; j++) {
        int idx = b * 1024 + t * 4 + j;
        if (idx < NN) g_rowptr[idx + 1] += add;
    }
    if (b == 0 && t == 0) g_rowptr[0] = 0;
}
__global__ void k_scatter(const int* __restrict__ src, const int* __restrict__ dst,
                          const float* __restrict__ w) {
    int e = blockIdx.x * blockDim.x + threadIdx.x;
    if (e < NE) {
        int d = dst[e];
        int pos = g_rowptr[d] + atomicAdd(&g_cur[d], 1);
        g_csrc[pos] = src[e];
        g_cw[pos] = w[e];
    }
}

// ---------------- weight prep (transpose + bf16 split) ---------------------
__device__ __forceinline__ void bsplit(float v, __nv_bfloat16& hi, __nv_bfloat16& lo) {
    hi = __float2bfloat16_rn(v);
    lo = __float2bfloat16_rn(v - __bfloat162float(hi));
}
__global__ void k_wprep9(const float* __restrict__ Wfc, const float* __restrict__ convw) {
    int idx = blockIdx.x * blockDim.x + threadIdx.x;
    if (idx >= 9 * 512 * 256) return;
    int m = idx / (512 * 256);
    int r = idx - m * 512 * 256;
    int k = r / 256, n = r - k * 256;
    float v = (m == 0) ? Wfc[r] : convw[(m - 1) * 512 * 256 + r];
    __nv_bfloat16 hi, lo; bsplit(v, hi, lo);
    size_t o = (size_t)m * 256 * 512 + (size_t)n * 512 + k;
    g_wt9_hi[o] = hi; g_wt9_lo[o] = lo;
}
__global__ void k_wprepd(const float* __restrict__ dynw) {
    int idx = blockIdx.x * blockDim.x + threadIdx.x;
    if (idx >= NL * 256 * 256) return;
    int i = idx / (256 * 256);
    int r = idx - i * 256 * 256;
    int k = r / 256, n = r - k * 256;
    const float* base = dynw + (size_t)i * 512 * 256;
    float v = base[k * 256 + n] - base[(k + 256) * 256 + n];
    __nv_bfloat16 hi, lo; bsplit(v, hi, lo);
    size_t o = (size_t)i * 256 * 256 + (size_t)n * 256 + k;
    g_wtd_hi[o] = hi; g_wtd_lo[o] = lo;
}
__global__ void k_convx(const float* __restrict__ x) {
    int idx = blockIdx.x * blockDim.x + threadIdx.x;
    if (idx >= NN * 512) return;
    __nv_bfloat16 hi, lo; bsplit(x[idx], hi, lo);
    g_bx_hi[idx] = hi; g_bx_lo[idx] = lo;
}

// ============ small-tile GEMM, BK=32 double-buffered ========================
// C[128 x 128-slice] = A[M,K] @ W^T, bf16 split, fp32 acc, 2 CTA/SM.
// MODE 0 fc  : v=relu(acc+bias); write C(hf), C2(h0f), Chi/Clo(bh0)
// MODE 1 conv: v=relu(theta*acc+(1-theta)*(0.9*Ehi+0.1*Eh0)+Eh); write C
// MODE 2 dyn : v=relu(acc+bias)+res*Eh0; write C(df), Chi/Clo
template <int MODE>
__device__ void gemm_block(
           int bx, int by,
           const __nv_bfloat16* __restrict__ A1h, const __nv_bfloat16* __restrict__ A1l, int s1,
           const __nv_bfloat16* __restrict__ A2h, const __nv_bfloat16* __restrict__ A2l, int s2,
           int K1, int K,
           const __nv_bfloat16* __restrict__ Bh, const __nv_bfloat16* __restrict__ Bl,
           float* __restrict__ C, const float* __restrict__ bias,
           const float* __restrict__ Ehi, const float* __restrict__ Eh0, const float* __restrict__ Eh,
           float theta, float res_scale,
           __nv_bfloat16* __restrict__ Chi, __nv_bfloat16* __restrict__ Clo,
           float* __restrict__ C2)
{
    extern __shared__ char smc[];
    uint32_t sb = smem_u32(smc);
    int t = threadIdx.x, lane = t & 31, wid = t >> 5;
    int widm = wid >> 2, widn = wid & 3;   // 2 x 4 warp grid
    int bn0 = bx * 128;
    int bm0 = by * 128;

    float acc[4][4][4];
#pragma unroll
    for (int a = 0; a < 4; a++)
#pragma unroll
        for (int b = 0; b < 4; b++)
#pragma unroll
            for (int c = 0; c < 4; c++) acc[a][b][c] = 0.f;

    const int nc = K / 32;

    int mi = lane >> 3;
    int arow_off = (lane & 7) + ((mi & 1) << 3);
    int akcol = (mi >> 1) << 4;
    int brow_off = (lane & 7);
    int bkcol = ((lane >> 3) & 1) << 4;

    auto load_chunk = [&](int ch, int buf) {
        uint32_t bb = sb + buf * BUFSZ;
        int kk0 = ch * 32;
#pragma unroll
        for (int j = 0; j < 2; j++) {
            int idx = t + j * 256;
            int r = idx >> 2, c16 = idx & 3;
            uint32_t d = SW64(r * 64 + c16 * 16);
            // A (possibly split across two sources at K1)
            int grow = bm0 + r;
            int kk = kk0 + c16 * 8;
            const __nv_bfloat16 *ph, *pl; int st;
            if (kk < K1) { ph = A1h; pl = A1l; st = s1; }
            else         { ph = A2h; pl = A2l; st = s2; kk -= K1; }
            int pred = 16;
            if (grow >= NN) { grow = 0; pred = 0; }
            cpasync16(bb + d,        ph + (size_t)grow * st + kk, pred);
            cpasync16(bb + 8192 + d, pl + (size_t)grow * st + kk, pred);
            // B (stride = K)
            size_t bo = (size_t)(bn0 + r) * K + kk0 + c16 * 8;
            cpasync16(bb + 16384 + d, Bh + bo, 16);
            cpasync16(bb + 24576 + d, Bl + bo, 16);
        }
        CP_COMMIT();
    };

    load_chunk(0, 0);
    for (int c = 0; c < nc; c++) {
        if (c + 1 < nc) { load_chunk(c + 1, (c + 1) & 1); CP_WAIT1(); }
        else            { CP_WAIT0(); }
        __syncthreads();
        uint32_t bb = sb + (c & 1) * BUFSZ;
#pragma unroll
        for (int ks = 0; ks < 2; ks++) {
            int kb = ks * 32;           // byte offset of k16 step within 64B row
            uint32_t Bh2[4][2], Bl2[4][2];
#pragma unroll
            for (int nt = 0; nt < 4; nt++) {
                int row = widn * 32 + nt * 8 + brow_off;
                uint32_t bd = bb + 16384 + SW64(row * 64 + kb + bkcol);
                ldx2(Bh2[nt], bd);
                ldx2(Bl2[nt], bd + 8192);
            }
#pragma unroll
            for (int mt = 0; mt < 4; mt++) {
                uint32_t Ah[4], Al[4];
                int row = widm * 64 + mt * 16 + arow_off;
                uint32_t ad = bb + SW64(row * 64 + kb + akcol);
                ldx4(Ah, ad);
                ldx4(Al, ad + 8192);
#pragma unroll
                for (int nt = 0; nt < 4; nt++) {
                    mma16816(acc[mt][nt], Ah, Bh2[nt]);
                    mma16816(acc[mt][nt], Ah, Bl2[nt]);
                    mma16816(acc[mt][nt], Al, Bh2[nt]);
                }
            }
        }
        __syncthreads();
    }

    // ---- epilogue ----
#pragma unroll
    for (int mt = 0; mt < 4; mt++) {
#pragma unroll
        for (int nt = 0; nt < 4; nt++) {
            int cb = bn0 + widn * 32 + nt * 8 + (lane & 3) * 2;
#pragma unroll
            for (int half = 0; half < 2; half++) {
                int row = bm0 + widm * 64 + mt * 16 + (lane >> 2) + half * 8;
                if (row >= NN) continue;
                size_t rb = (size_t)row * H + cb;
                float v0 = acc[mt][nt][half * 2 + 0];
                float v1 = acc[mt][nt][half * 2 + 1];
                if (MODE == 0) {
                    v0 = fmaxf(v0 + bias[cb], 0.f);
                    v1 = fmaxf(v1 + bias[cb + 1], 0.f);
                } else if (MODE == 1) {
                    float2 e1 = *(const float2*)(Ehi + rb);
                    float2 e2 = *(const float2*)(Eh0 + rb);
                    float2 e3 = *(const float2*)(Eh + rb);
                    v0 = fmaxf(theta * v0 + (1.f - theta) * (0.9f * e1.x + 0.1f * e2.x) + e3.x, 0.f);
                    v1 = fmaxf(theta * v1 + (1.f - theta) * (0.9f * e1.y + 0.1f * e2.y) + e3.y, 0.f);
                } else {
                    float2 e2 = *(const float2*)(Eh0 + rb);
                    v0 = fmaxf(v0 + bias[cb], 0.f) + res_scale * e2.x;
                    v1 = fmaxf(v1 + bias[cb + 1], 0.f) + res_scale * e2.y;
                }
                *(float2*)(C + rb) = make_float2(v0, v1);
                if (MODE == 0) *(float2*)(C2 + rb) = make_float2(v0, v1);
                if (MODE == 0 || MODE == 2) {
                    union { uint32_t u; __nv_bfloat16 b[2]; } ph_, pl_;
                    __nv_bfloat16 h0b = __float2bfloat16_rn(v0);
                    __nv_bfloat16 h1b = __float2bfloat16_rn(v1);
                    ph_.b[0] = h0b; ph_.b[1] = h1b;
                    pl_.b[0] = __float2bfloat16_rn(v0 - __bfloat162float(h0b));
                    pl_.b[1] = __float2bfloat16_rn(v1 - __bfloat162float(h1b));
                    *(uint32_t*)(Chi + rb) = ph_.u;
                    *(uint32_t*)(Clo + rb) = pl_.u;
                }
            }
        }
    }
}

template <int MODE>
__global__ void __launch_bounds__(256, 2)
k_gemm(const __nv_bfloat16* A1h, const __nv_bfloat16* A1l, int s1,
       const __nv_bfloat16* A2h, const __nv_bfloat16* A2l, int s2,
       int K1, int K,
       const __nv_bfloat16* Bh, const __nv_bfloat16* Bl,
       float* C, const float* bias,
       const float* Ehi, const float* Eh0, const float* Eh,
       float theta, float res_scale,
       __nv_bfloat16* Chi, __nv_bfloat16* Clo, float* C2)
{
    gemm_block<MODE>(blockIdx.x, blockIdx.y, A1h, A1l, s1, A2h, A2l, s2, K1, K,
                     Bh, Bl, C, bias, Ehi, Eh0, Eh, theta, res_scale, Chi, Clo, C2);
}

// ---------------- SpMM block (device function) ------------------------------
__device__ void spmm_block(int node_base, const float* __restrict__ h,
                           float* __restrict__ hif,
                           __nv_bfloat16* __restrict__ bhih,
                           __nv_bfloat16* __restrict__ bhil) {
    int wid = threadIdx.x >> 5, lane = threadIdx.x & 31;
    int node = node_base + wid;
    if (node >= NN) return;
    int s0 = g_rowptr[node], s1 = g_rowptr[node + 1];
    float4 a0 = make_float4(0.f, 0.f, 0.f, 0.f);
    float4 a1 = make_float4(0.f, 0.f, 0.f, 0.f);
    const float4* h4 = (const float4*)h;
    int e = s0;
    for (; e + 3 < s1; e += 4) {
        int si[4]; float w[4];
#pragma unroll
        for (int u = 0; u < 4; u++) { si[u] = g_csrc[e + u]; w[u] = g_cw[e + u]; }
        float4 v0[4], v1[4];
#pragma unroll
        for (int u = 0; u < 4; u++) {
            const float4* p = h4 + (size_t)si[u] * 64;
            v0[u] = __ldg(p + lane);
            v1[u] = __ldg(p + lane + 32);
        }
#pragma unroll
        for (int u = 0; u < 4; u++) {
            a0.x += w[u] * v0[u].x; a0.y += w[u] * v0[u].y;
            a0.z += w[u] * v0[u].z; a0.w += w[u] * v0[u].w;
            a1.x += w[u] * v1[u].x; a1.y += w[u] * v1[u].y;
            a1.z += w[u] * v1[u].z; a1.w += w[u] * v1[u].w;
        }
    }
    for (; e < s1; e++) {
        int sA = g_csrc[e];
        float wA = g_cw[e];
        const float4* pA = h4 + (size_t)sA * 64;
        float4 vA0 = __ldg(pA + lane), vA1 = __ldg(pA + lane + 32);
        a0.x += wA * vA0.x; a0.y += wA * vA0.y; a0.z += wA * vA0.z; a0.w += wA * vA0.w;
        a1.x += wA * vA1.x; a1.y += wA * vA1.y; a1.z += wA * vA1.z; a1.w += wA * vA1.w;
    }
    float4* op = (float4*)hif + (size_t)node * 64;
    op[lane] = a0;
    op[lane + 32] = a1;
    size_t rb = (size_t)node * H;
    union { uint2 u; __nv_bfloat16 b[4]; } ph_, pl_;
    float va[4] = {a0.x, a0.y, a0.z, a0.w};
#pragma unroll
    for (int i = 0; i < 4; i++) {
        __nv_bfloat16 hb = __float2bfloat16_rn(va[i]);
        ph_.b[i] = hb; pl_.b[i] = __float2bfloat16_rn(va[i] - __bfloat162float(hb));
    }
    *(uint2*)(bhih + rb + lane * 4) = ph_.u;
    *(uint2*)(bhil + rb + lane * 4) = pl_.u;
    float vb[4] = {a1.x, a1.y, a1.z, a1.w};
#pragma unroll
    for (int i = 0; i < 4; i++) {
        __nv_bfloat16 hb = __float2bfloat16_rn(vb[i]);
        ph_.b[i] = hb; pl_.b[i] = __float2bfloat16_rn(vb[i] - __bfloat162float(hb));
    }
    *(uint2*)(bhih + rb + 128 + lane * 4) = ph_.u;
    *(uint2*)(bhil + rb + 128 + lane * 4) = pl_.u;
}

// ---------------- fused SpMM + dyn-GEMM (R6-proven interleave) --------------
#define NGEMMB 1564
#define FUSED_GRID 14076     // 1564 * 9; every 9th block = dyn GEMM
__global__ void __launch_bounds__(256, 2)
k_sd(const __nv_bfloat16* dinh, const __nv_bfloat16* dinl,
     const __nv_bfloat16* wdh, const __nv_bfloat16* wdl,
     float* df, const float* dynb, const float* h0f, float res_scale,
     __nv_bfloat16* douh, __nv_bfloat16* doul,
     const float* hf, float* hif, __nv_bfloat16* bhih, __nv_bfloat16* bhil)
{
    int bid = blockIdx.x;
    if (bid % 9 == 0) {
        int gid = bid / 9;
        if (gid < NGEMMB)
            gemm_block<2>(gid & 1, gid >> 1,
                          dinh, dinl, 256, (const __nv_bfloat16*)nullptr, (const __nv_bfloat16*)nullptr, 0,
                          1 << 30, 256, wdh, wdl,
                          df, dynb, nullptr, h0f, nullptr, 0.f, res_scale,
                          douh, doul, nullptr);
    } else {
        int sid = bid - bid / 9 - 1;
        if (sid < NN / 8)
            spmm_block(sid * 8, hf, hif, bhih, bhil);
    }
}

// ---------------- merged LN-cross + out GEMM + log_softmax ------------------
__device__ __forceinline__ float warp_sum(float v) {
#pragma unroll
    for (int off = 16; off; off >>= 1) v += __shfl_xor_sync(0xffffffffu, v, off);
    return v;
}

__global__ void __launch_bounds__(256) k_crossout(
    const float* __restrict__ h, const float* __restrict__ d,
    const float* __restrict__ g1, const float* __restrict__ b1,
    const float* __restrict__ g2, const float* __restrict__ b2,
    const float* __restrict__ Wout, const float* __restrict__ bout,
    float* __restrict__ out, float* __restrict__ cross_out)
{
    __shared__ float Ws[256 * 41];
    __shared__ float bs[NC];
    int t = threadIdx.x;
    for (int i = t; i < 256 * NC; i += 256) {
        int k = i / NC, c = i - k * NC;
        Ws[k * 41 + c] = Wout[i];
    }
    if (t < NC) bs[t] = bout[t];
    __syncthreads();

    int row = blockIdx.x * 8 + (t >> 5);
    int lane = t & 31;
    if (row >= NN) return;
    size_t rb = (size_t)row * H;

    float hv[8], dv[8];
#pragma unroll
    for (int r = 0; r < 8; r++) {
        int k = lane + 32 * r;
        hv[r] = h[rb + k];
        dv[r] = d[rb + k];
    }
    float sh = 0.f, sd = 0.f;
#pragma unroll
    for (int r = 0; r < 8; r++) { sh += hv[r]; sd += dv[r]; }
    sh = warp_sum(sh); sd = warp_sum(sd);
    float m1 = sh * (1.f / 256.f), m2 = sd * (1.f / 256.f);
    float q1 = 0.f, q2 = 0.f;
#pragma unroll
    for (int r = 0; r < 8; r++) {
        float e1 = hv[r] - m1; q1 += e1 * e1;
        float e2 = dv[r] - m2; q2 += e2 * e2;
    }
    q1 = warp_sum(q1); q2 = warp_sum(q2);
    float i1 = rsqrtf(q1 * (1.f / 256.f) + 1e-6f);
    float i2 = rsqrtf(q2 * (1.f / 256.f) + 1e-6f);

    float v[8];
#pragma unroll
    for (int r = 0; r < 8; r++) {
        int k = lane + 32 * r;
        v[r] = g1[k] * (hv[r] - m1) * i1 + b1[k] + g2[k] * (dv[r] - m2) * i2 + b2[k];
        if (cross_out) cross_out[rb + k] = v[r];
    }

    float acc[NC];
#pragma unroll
    for (int c = 0; c < NC; c++) acc[c] = 0.f;
#pragma unroll
    for (int r = 0; r < 8; r++) {
        int k = lane + 32 * r;
        const float* wr = &Ws[k * 41];
#pragma unroll
        for (int c = 0; c < NC; c++) acc[c] += v[r] * wr[c];
    }
#pragma unroll
    for (int c = 0; c < NC; c++)
#pragma unroll
        for (int off = 16; off; off >>= 1) acc[c] += __shfl_xor_sync(0xffffffffu, acc[c], off);

    float m = -1e30f;
#pragma unroll
    for (int c = 0; c < NC; c++) { acc[c] += bs[c]; m = fmaxf(m, acc[c]); }
    float s = 0.f;
#pragma unroll
    for (int c = 0; c < NC; c++) s += expf(acc[c] - m);
    float lse = m + logf(s);
    float* o = out + (size_t)row * NC;
#pragma unroll
    for (int c = 0; c < NC; c++)
        if ((c & 31) == lane) o[c] = acc[c] - lse;
}

// ---------------- launch ---------------------------------------------------
extern "C" void kernel_launch(void* const* d_in, const int* in_sizes, int n_in,
                              void* d_out, int out_size)
{
    const float* x     = (const float*)d_in[0];
    const int*   esrc  = (const int*)d_in[1];
    const int*   edst  = (const int*)d_in[2];
    const float* ew    = (const float*)d_in[3];
    const float* Wfc   = (const float*)d_in[4];
    const float* bfc   = (const float*)d_in[5];
    const float* convw = (const float*)d_in[6];
    const float* dynw  = (const float*)d_in[7];
    const float* dynb  = (const float*)d_in[8];
    const float* g1    = (const float*)d_in[9];
    const float* b1    = (const float*)d_in[10];
    const float* g2    = (const float*)d_in[11];
    const float* b2    = (const float*)d_in[12];
    const float* Wout  = (const float*)d_in[13];
    const float* bout  = (const float*)d_in[14];
    float* out = (float*)d_out;

    float *h0f, *hf, *hif, *df;
    cudaGetSymbolAddress((void**)&h0f, g_h0f);
    cudaGetSymbolAddress((void**)&hf,  g_hf);
    cudaGetSymbolAddress((void**)&hif, g_hif);
    cudaGetSymbolAddress((void**)&df,  g_df);
    __nv_bfloat16 *bxh, *bxl, *bh0h, *bh0l, *bhih, *bhil, *bdAh, *bdAl, *bdBh, *bdBl, *w9h, *w9l, *wdh, *wdl;
    cudaGetSymbolAddress((void**)&bxh, g_bx_hi);
    cudaGetSymbolAddress((void**)&bxl, g_bx_lo);
    cudaGetSymbolAddress((void**)&bh0h, g_bh0_hi);
    cudaGetSymbolAddress((void**)&bh0l, g_bh0_lo);
    cudaGetSymbolAddress((void**)&bhih, g_bhi_hi);
    cudaGetSymbolAddress((void**)&bhil, g_bhi_lo);
    cudaGetSymbolAddress((void**)&bdAh, g_bdA_hi);
    cudaGetSymbolAddress((void**)&bdAl, g_bdA_lo);
    cudaGetSymbolAddress((void**)&bdBh, g_bdB_hi);
    cudaGetSymbolAddress((void**)&bdBl, g_bdB_lo);
    cudaGetSymbolAddress((void**)&w9h, g_wt9_hi);
    cudaGetSymbolAddress((void**)&w9l, g_wt9_lo);
    cudaGetSymbolAddress((void**)&wdh, g_wtd_hi);
    cudaGetSymbolAddress((void**)&wdl, g_wtd_lo);

    cudaFuncSetAttribute(k_gemm<0>, cudaFuncAttributeMaxDynamicSharedMemorySize, SMEM_TOTAL);
    cudaFuncSetAttribute(k_gemm<1>, cudaFuncAttributeMaxDynamicSharedMemorySize, SMEM_TOTAL);
    cudaFuncSetAttribute(k_sd,      cudaFuncAttributeMaxDynamicSharedMemorySize, SMEM_TOTAL);

    const int BIGK = 1 << 30;
    dim3 grid(2, GRID_M);

    // prep
    k_convx<<<(NN * 512 + 255) / 256, 256>>>(x);
    k_wprep9<<<(9 * 512 * 256 + 255) / 256, 256>>>(Wfc, convw);
    k_wprepd<<<(NL * 256 * 256 + 255) / 256, 256>>>(dynw);

    // fc: h = h0 = relu(x@Wfc + bfc)
    k_gemm<0><<<grid, 256, SMEM_TOTAL>>>(
        bxh, bxl, 512, (const __nv_bfloat16*)nullptr, (const __nv_bfloat16*)nullptr, 0,
        BIGK, 512, w9h, w9l,
        hf, bfc, nullptr, nullptr, nullptr, 0.f, 0.f,
        bh0h, bh0l, h0f);

    // CSR build (independent of fc)
    k_zero<<<(NN + 255) / 256, 256>>>();
    k_hist<<<NE / 256, 256>>>(edst);
    k_scan1<<<98, 256>>>();
    k_scan2<<<1, 128>>>(98);
    k_scan3<<<98, 256>>>();
    k_scatter<<<NE / 256, 256>>>(esrc, edst, ew);

    for (int i = 0; i < NL; i++) {
        const __nv_bfloat16* dinh = (i == 0) ? bh0h : ((i & 1) ? bdAh : bdBh);
        const __nv_bfloat16* dinl = (i == 0) ? bh0l : ((i & 1) ? bdAl : bdBl);
        __nv_bfloat16* douh = (i & 1) ? bdBh : bdAh;
        __nv_bfloat16* doul = (i & 1) ? bdBl : bdAl;

        // fused: SpMM(h -> hi) overlapped with dyn GEMM (d -> d_next)
        k_sd<<<FUSED_GRID, 256, SMEM_TOTAL>>>(
            dinh, dinl, wdh + (size_t)i * 256 * 256, wdl + (size_t)i * 256 * 256,
            df, dynb + (size_t)i * H, h0f, (i > 0) ? 0.1f : 0.f,
            douh, doul,
            hf, hif, bhih, bhil);

        float theta = logf(0.5f / (float)(i + 1) + 1.0f);
        // conv: h = relu(theta*([hi|h0]@convw_i) + (1-theta)*(0.9*hi+0.1*h0) + h)
        k_gemm<1><<<grid, 256, SMEM_TOTAL>>>(
            bhih, bhil, 256, bh0h, bh0l, 256,
            256, 512, w9h + (size_t)(1 + i) * 256 * 512, w9l + (size_t)(1 + i) * 256 * 512,
            hf, nullptr, hif, h0f, hf, theta, 0.f,
            nullptr, nullptr, nullptr);
    }

    float* cross_out_ptr = (out_size >= NN * (NC + H)) ? (out + (size_t)NN * NC) : nullptr;
    k_crossout<<<NN / 8, 256>>>(hf, df, g1, b1, g2, b2, Wout, bout, out, cross_out_ptr);
}

// round 15
// speedup vs baseline: 1.1760x; 1.1211x over previous
#include <cuda_runtime.h>
#include <cuda_bf16.h>
#include <cuda_fp16.h>
#include <math.h>
#include <stdint.h>

#define NN 100000
#define NE 3200000
#define H  256
#define NC 40
#define NL 8
#define MPAD 100096          // 782 * 128
#define GRID_M 782

// ---------------- device scratch (no allocations allowed) ------------------
__device__ int   g_deg[NN];
__device__ int   g_cur[NN];
__device__ int   g_rowptr[NN + 1];
__device__ int   g_bsums[128];
__device__ int   g_csrc[NE];
__device__ float g_cw[NE];

__device__ float g_h0f[MPAD * H];
__device__ float g_hf [MPAD * H];
__device__ float g_df [MPAD * H];
__device__ __half g_hq [MPAD * H];    // h in fp16 (SpMM gather source)

__device__ __nv_bfloat16 g_bx_hi[MPAD * 512];
__device__ __nv_bfloat16 g_bx_lo[MPAD * 512];
__device__ __nv_bfloat16 g_bh0_hi[MPAD * H];
__device__ __nv_bfloat16 g_bh0_lo[MPAD * H];
__device__ __nv_bfloat16 g_bhi_hi[MPAD * H];
__device__ __nv_bfloat16 g_bhi_lo[MPAD * H];
__device__ __nv_bfloat16 g_bdA_hi[MPAD * H];
__device__ __nv_bfloat16 g_bdA_lo[MPAD * H];
__device__ __nv_bfloat16 g_bdB_hi[MPAD * H];
__device__ __nv_bfloat16 g_bdB_lo[MPAD * H];

// weights, pre-transposed to [N=256][K] row-major, bf16 split
__device__ __nv_bfloat16 g_wt9_hi[9 * H * 512];   // fc + 8 conv (K=512)
__device__ __nv_bfloat16 g_wt9_lo[9 * H * 512];
__device__ __nv_bfloat16 g_wtd_hi[NL * H * H];    // dyn effective (K=256)
__device__ __nv_bfloat16 g_wtd_lo[NL * H * H];

// ---------------- helpers --------------------------------------------------
__device__ __forceinline__ uint32_t smem_u32(const void* p) {
    uint32_t a;
    asm("{ .reg .u64 t; cvta.to.shared.u64 t, %1; cvt.u32.u64 %0, t; }" : "=r"(a) : "l"(p));
    return a;
}
#define SW128(o) ((o) ^ (((o) >> 3) & 0x70))

__device__ __forceinline__ void cpasync16(uint32_t dst, const void* src, int srcsize) {
    uint64_t g = __cvta_generic_to_global(src);
    asm volatile("cp.async.cg.shared.global [%0], [%1], 16, %2;"
                 :: "r"(dst), "l"(g), "r"(srcsize) : "memory");
}
#define CP_COMMIT() asm volatile("cp.async.commit_group;" ::: "memory")
#define CP_WAIT0()  asm volatile("cp.async.wait_group 0;" ::: "memory")

__device__ __forceinline__ void ldx4(uint32_t* r, uint32_t addr) {
    asm volatile("ldmatrix.sync.aligned.m8n8.x4.shared.b16 {%0,%1,%2,%3}, [%4];"
                 : "=r"(r[0]), "=r"(r[1]), "=r"(r[2]), "=r"(r[3]) : "r"(addr));
}
__device__ __forceinline__ void ldx2(uint32_t* r, uint32_t addr) {
    asm volatile("ldmatrix.sync.aligned.m8n8.x2.shared.b16 {%0,%1}, [%2];"
                 : "=r"(r[0]), "=r"(r[1]) : "r"(addr));
}
__device__ __forceinline__ void mma16816(float* c, const uint32_t* a, const uint32_t* b) {
    asm volatile("mma.sync.aligned.m16n8k16.row.col.f32.bf16.bf16.f32 "
                 "{%0,%1,%2,%3}, {%4,%5,%6,%7}, {%8,%9}, {%0,%1,%2,%3};"
                 : "+f"(c[0]), "+f"(c[1]), "+f"(c[2]), "+f"(c[3])
                 : "r"(a[0]), "r"(a[1]), "r"(a[2]), "r"(a[3]), "r"(b[0]), "r"(b[1]));
}

// smem: single 64KB buffer: [Ahi 16K][Alo 16K][Bhi 16K][Blo 16K]
#define SMEM_TOTAL 65536

// ---------------- CSR build ------------------------------------------------
__global__ void k_zero() {
    int i = blockIdx.x * blockDim.x + threadIdx.x;
    if (i < NN) { g_deg[i] = 0; g_cur[i] = 0; }
}
__global__ void k_hist(const int* __restrict__ dst) {
    int e = blockIdx.x * blockDim.x + threadIdx.x;
    if (e < NE) atomicAdd(&g_deg[dst[e]], 1);
}
__global__ void k_scan1() {
    __shared__ int sh[256];
    int b = blockIdx.x, t = threadIdx.x;
    int base = b * 1024 + t * 4;
    int v[4], loc[4];
#pragma unroll
    for (int j = 0; j < 4; j++) { int idx = base + j; v[j] = (idx < NN) ? g_deg[idx] : 0; }
    loc[0] = v[0];
#pragma unroll
    for (int j = 1; j < 4; j++) loc[j] = loc[j - 1] + v[j];
    sh[t] = loc[3];
    __syncthreads();
    for (int off = 1; off < 256; off <<= 1) {
        int x = (t >= off) ? sh[t - off] : 0;
        __syncthreads();
        sh[t] += x;
        __syncthreads();
    }
    int pre = (t > 0) ? sh[t - 1] : 0;
#pragma unroll
    for (int j = 0; j < 4; j++) { int idx = base + j; if (idx < NN) g_rowptr[idx + 1] = pre + loc[j]; }
    if (t == 255) g_bsums[b] = sh[255];
}
__global__ void k_scan2(int nb) {
    __shared__ int sh[128];
    int t = threadIdx.x;
    sh[t] = (t < nb) ? g_bsums[t] : 0;
    __syncthreads();
    for (int off = 1; off < 128; off <<= 1) {
        int x = (t >= off) ? sh[t - off] : 0;
        __syncthreads();
        sh[t] += x;
        __syncthreads();
    }
    g_bsums[t] = sh[t];
}
__global__ void k_scan3() {
    int b = blockIdx.x, t = threadIdx.x;
    int add = (b > 0) ? g_bsums[b - 1] : 0;
#pragma unroll
    for (int j = 0; j < 4; j++) {
        int idx = b * 1024 + t * 4 + j;
        if (idx < NN) g_rowptr[idx + 1] += add;
    }
    if (b == 0 && t == 0) g_rowptr[0] = 0;
}
__global__ void k_scatter(const int* __restrict__ src, const int* __restrict__ dst,
                          const float* __restrict__ w) {
    int e = blockIdx.x * blockDim.x + threadIdx.x;
    if (e < NE) {
        int d = dst[e];
        int pos = g_rowptr[d] + atomicAdd(&g_cur[d], 1);
        g_csrc[pos] = src[e];
        g_cw[pos] = w[e];
    }
}

// ---------------- weight prep (transpose + bf16 split) ---------------------
__device__ __forceinline__ void bsplit(float v, __nv_bfloat16& hi, __nv_bfloat16& lo) {
    hi = __float2bfloat16_rn(v);
    lo = __float2bfloat16_rn(v - __bfloat162float(hi));
}
__global__ void k_wprep9(const float* __restrict__ Wfc, const float* __restrict__ convw) {
    int idx = blockIdx.x * blockDim.x + threadIdx.x;
    if (idx >= 9 * 512 * 256) return;
    int m = idx / (512 * 256);
    int r = idx - m * 512 * 256;
    int k = r / 256, n = r - k * 256;
    float v = (m == 0) ? Wfc[r] : convw[(m - 1) * 512 * 256 + r];
    __nv_bfloat16 hi, lo; bsplit(v, hi, lo);
    size_t o = (size_t)m * 256 * 512 + (size_t)n * 512 + k;
    g_wt9_hi[o] = hi; g_wt9_lo[o] = lo;
}
__global__ void k_wprepd(const float* __restrict__ dynw) {
    int idx = blockIdx.x * blockDim.x + threadIdx.x;
    if (idx >= NL * 256 * 256) return;
    int i = idx / (256 * 256);
    int r = idx - i * 256 * 256;
    int k = r / 256, n = r - k * 256;
    const float* base = dynw + (size_t)i * 512 * 256;
    float v = base[k * 256 + n] - base[(k + 256) * 256 + n];
    __nv_bfloat16 hi, lo; bsplit(v, hi, lo);
    size_t o = (size_t)i * 256 * 256 + (size_t)n * 256 + k;
    g_wtd_hi[o] = hi; g_wtd_lo[o] = lo;
}
__global__ void k_convx(const float* __restrict__ x) {
    int idx = blockIdx.x * blockDim.x + threadIdx.x;
    if (idx >= NN * 512) return;
    __nv_bfloat16 hi, lo; bsplit(x[idx], hi, lo);
    g_bx_hi[idx] = hi; g_bx_lo[idx] = lo;
}

// ============ small-tile GEMM block (R6-proven: BK=64, single 64KB buf) =====
// MODE 0 fc  : v=relu(acc+bias); write C(hf), C2(h0f), Chi/Clo(bh0), Cf16(hq)
// MODE 1 conv: e1 = Ehih+Ehil (bf16 pair of hi);
//              v=relu(theta*acc+(1-theta)*(0.9*e1+0.1*Eh0)+Eh); write C(hf), Cf16(hq)
// MODE 2 dyn : v=relu(acc+bias)+res*Eh0; write C(df), Chi/Clo
template <int MODE>
__device__ void gemm_block(
           int bx, int by,
           const __nv_bfloat16* __restrict__ A1h, const __nv_bfloat16* __restrict__ A1l, int s1,
           const __nv_bfloat16* __restrict__ A2h, const __nv_bfloat16* __restrict__ A2l, int s2,
           int K1, int K,
           const __nv_bfloat16* __restrict__ Bh, const __nv_bfloat16* __restrict__ Bl,
           float* __restrict__ C, const float* __restrict__ bias,
           const __nv_bfloat16* __restrict__ Ehih, const __nv_bfloat16* __restrict__ Ehil,
           const float* __restrict__ Eh0, const float* __restrict__ Eh,
           float theta, float res_scale,
           __nv_bfloat16* __restrict__ Chi, __nv_bfloat16* __restrict__ Clo,
           float* __restrict__ C2, __half* __restrict__ Cf16)
{
    extern __shared__ char smc[];
    uint32_t sb = smem_u32(smc);
    int t = threadIdx.x, lane = t & 31, wid = t >> 5;
    int widm = wid >> 2, widn = wid & 3;   // 2 x 4 warp grid
    int bn0 = bx * 128;
    int bm0 = by * 128;

    float acc[4][4][4];
#pragma unroll
    for (int a = 0; a < 4; a++)
#pragma unroll
        for (int b = 0; b < 4; b++)
#pragma unroll
            for (int c = 0; c < 4; c++) acc[a][b][c] = 0.f;

    const int nc = K / 64;

    int mi = lane >> 3;
    int arow_off = (lane & 7) + ((mi & 1) << 3);
    int akcol = (mi >> 1) << 4;
    int brow_off = (lane & 7);
    int bkcol = ((lane >> 3) & 1) << 4;

    for (int c = 0; c < nc; c++) {
        {
            int kk0 = c * 64;
#pragma unroll
            for (int j = 0; j < 4; j++) {
                int idx = t + j * 256;
                int r = idx >> 3, c16 = idx & 7;
                uint32_t d = SW128(r * 128 + c16 * 16);
                int grow = bm0 + r;
                int kk = kk0 + c16 * 8;
                const __nv_bfloat16 *ph, *pl; int st;
                if (kk < K1) { ph = A1h; pl = A1l; st = s1; }
                else         { ph = A2h; pl = A2l; st = s2; kk -= K1; }
                int pred = 16;
                if (grow >= NN) { grow = 0; pred = 0; }
                cpasync16(sb + d,         ph + (size_t)grow * st + kk, pred);
                cpasync16(sb + 16384 + d, pl + (size_t)grow * st + kk, pred);
                size_t bo = (size_t)(bn0 + r) * K + kk0 + c16 * 8;
                cpasync16(sb + 32768 + d, Bh + bo, 16);
                cpasync16(sb + 49152 + d, Bl + bo, 16);
            }
            CP_COMMIT();
        }
        CP_WAIT0();
        __syncthreads();
#pragma unroll
        for (int ks = 0; ks < 4; ks++) {
            int kb = ks * 32;
            uint32_t Bh2[4][2], Bl2[4][2];
#pragma unroll
            for (int nt = 0; nt < 4; nt++) {
                int row = widn * 32 + nt * 8 + brow_off;
                uint32_t bd = sb + 32768 + SW128(row * 128 + kb + bkcol);
                ldx2(Bh2[nt], bd);
                ldx2(Bl2[nt], bd + 16384);
            }
#pragma unroll
            for (int mt = 0; mt < 4; mt++) {
                uint32_t Ah[4], Al[4];
                int row = widm * 64 + mt * 16 + arow_off;
                uint32_t ad = sb + SW128(row * 128 + kb + akcol);
                ldx4(Ah, ad);
                ldx4(Al, ad + 16384);
#pragma unroll
                for (int nt = 0; nt < 4; nt++) {
                    mma16816(acc[mt][nt], Ah, Bh2[nt]);
                    mma16816(acc[mt][nt], Ah, Bl2[nt]);
                    mma16816(acc[mt][nt], Al, Bh2[nt]);
                }
            }
        }
        __syncthreads();
    }

    // ---- epilogue ----
#pragma unroll
    for (int mt = 0; mt < 4; mt++) {
#pragma unroll
        for (int nt = 0; nt < 4; nt++) {
            int cb = bn0 + widn * 32 + nt * 8 + (lane & 3) * 2;
#pragma unroll
            for (int half = 0; half < 2; half++) {
                int row = bm0 + widm * 64 + mt * 16 + (lane >> 2) + half * 8;
                if (row >= NN) continue;
                size_t rb = (size_t)row * H + cb;
                float v0 = acc[mt][nt][half * 2 + 0];
                float v1 = acc[mt][nt][half * 2 + 1];
                if (MODE == 0) {
                    v0 = fmaxf(v0 + bias[cb], 0.f);
                    v1 = fmaxf(v1 + bias[cb + 1], 0.f);
                } else if (MODE == 1) {
                    __nv_bfloat162 hh = *(const __nv_bfloat162*)(Ehih + rb);
                    __nv_bfloat162 hl = *(const __nv_bfloat162*)(Ehil + rb);
                    float e1x = __bfloat162float(hh.x) + __bfloat162float(hl.x);
                    float e1y = __bfloat162float(hh.y) + __bfloat162float(hl.y);
                    float2 e2 = *(const float2*)(Eh0 + rb);
                    float2 e3 = *(const float2*)(Eh + rb);
                    v0 = fmaxf(theta * v0 + (1.f - theta) * (0.9f * e1x + 0.1f * e2.x) + e3.x, 0.f);
                    v1 = fmaxf(theta * v1 + (1.f - theta) * (0.9f * e1y + 0.1f * e2.y) + e3.y, 0.f);
                } else {
                    float2 e2 = *(const float2*)(Eh0 + rb);
                    v0 = fmaxf(v0 + bias[cb], 0.f) + res_scale * e2.x;
                    v1 = fmaxf(v1 + bias[cb + 1], 0.f) + res_scale * e2.y;
                }
                *(float2*)(C + rb) = make_float2(v0, v1);
                if (MODE == 0) *(float2*)(C2 + rb) = make_float2(v0, v1);
                if (MODE == 0 || MODE == 1) {
                    *(__half2*)(Cf16 + rb) = __floats2half2_rn(v0, v1);
                }
                if (MODE == 0 || MODE == 2) {
                    union { uint32_t u; __nv_bfloat16 b[2]; } ph_, pl_;
                    __nv_bfloat16 h0b = __float2bfloat16_rn(v0);
                    __nv_bfloat16 h1b = __float2bfloat16_rn(v1);
                    ph_.b[0] = h0b; ph_.b[1] = h1b;
                    pl_.b[0] = __float2bfloat16_rn(v0 - __bfloat162float(h0b));
                    pl_.b[1] = __float2bfloat16_rn(v1 - __bfloat162float(h1b));
                    *(uint32_t*)(Chi + rb) = ph_.u;
                    *(uint32_t*)(Clo + rb) = pl_.u;
                }
            }
        }
    }
}

template <int MODE>
__global__ void __launch_bounds__(256, 2)
k_gemm(const __nv_bfloat16* A1h, const __nv_bfloat16* A1l, int s1,
       const __nv_bfloat16* A2h, const __nv_bfloat16* A2l, int s2,
       int K1, int K,
       const __nv_bfloat16* Bh, const __nv_bfloat16* Bl,
       float* C, const float* bias,
       const __nv_bfloat16* Ehih, const __nv_bfloat16* Ehil,
       const float* Eh0, const float* Eh,
       float theta, float res_scale,
       __nv_bfloat16* Chi, __nv_bfloat16* Clo, float* C2, __half* Cf16)
{
    gemm_block<MODE>(blockIdx.x, blockIdx.y, A1h, A1l, s1, A2h, A2l, s2, K1, K,
                     Bh, Bl, C, bias, Ehih, Ehil, Eh0, Eh, theta, res_scale,
                     Chi, Clo, C2, Cf16);
}

// ---------------- SpMM block: fp16 gather, bf16-pair output -----------------
// each lane owns 8 contiguous channels; per edge one 16B load per lane.
__device__ void spmm_block(int node_base, const __half* __restrict__ hq,
                           __nv_bfloat16* __restrict__ bhih,
                           __nv_bfloat16* __restrict__ bhil) {
    int wid = threadIdx.x >> 5, lane = threadIdx.x & 31;
    int node = node_base + wid;
    if (node >= NN) return;
    int s0 = g_rowptr[node], s1 = g_rowptr[node + 1];
    float a[8];
#pragma unroll
    for (int i = 0; i < 8; i++) a[i] = 0.f;
    const uint4* hq4 = (const uint4*)hq;   // 8 halves per uint4; 32 uint4 per row
    int e = s0;
    for (; e + 3 < s1; e += 4) {
        int si[4]; float w[4]; uint4 v[4];
#pragma unroll
        for (int u = 0; u < 4; u++) { si[u] = g_csrc[e + u]; w[u] = g_cw[e + u]; }
#pragma unroll
        for (int u = 0; u < 4; u++)
            v[u] = __ldg(hq4 + (size_t)si[u] * 32 + lane);
#pragma unroll
        for (int u = 0; u < 4; u++) {
            const __half2* p2 = (const __half2*)&v[u];
#pragma unroll
            for (int q = 0; q < 4; q++) {
                float2 f = __half22float2(p2[q]);
                a[q * 2 + 0] += w[u] * f.x;
                a[q * 2 + 1] += w[u] * f.y;
            }
        }
    }
    for (; e < s1; e++) {
        int sA = g_csrc[e];
        float wA = g_cw[e];
        uint4 v = __ldg(hq4 + (size_t)sA * 32 + lane);
        const __half2* p2 = (const __half2*)&v;
#pragma unroll
        for (int q = 0; q < 4; q++) {
            float2 f = __half22float2(p2[q]);
            a[q * 2 + 0] += wA * f.x;
            a[q * 2 + 1] += wA * f.y;
        }
    }
    size_t rb = (size_t)node * H + lane * 8;
    union { uint4 u; __nv_bfloat16 b[8]; } ph_, pl_;
#pragma unroll
    for (int i = 0; i < 8; i++) {
        __nv_bfloat16 hb = __float2bfloat16_rn(a[i]);
        ph_.b[i] = hb;
        pl_.b[i] = __float2bfloat16_rn(a[i] - __bfloat162float(hb));
    }
    *(uint4*)(bhih + rb) = ph_.u;
    *(uint4*)(bhil + rb) = pl_.u;
}

// ---------------- fused SpMM + dyn-GEMM (R6-proven interleave) --------------
#define NGEMMB 1564
#define FUSED_GRID 14076     // 1564 * 9; every 9th block = dyn GEMM
__global__ void __launch_bounds__(256, 2)
k_sd(const __nv_bfloat16* dinh, const __nv_bfloat16* dinl,
     const __nv_bfloat16* wdh, const __nv_bfloat16* wdl,
     float* df, const float* dynb, const float* h0f, float res_scale,
     __nv_bfloat16* douh, __nv_bfloat16* doul,
     const __half* hq, __nv_bfloat16* bhih, __nv_bfloat16* bhil)
{
    int bid = blockIdx.x;
    if (bid % 9 == 0) {
        int gid = bid / 9;
        if (gid < NGEMMB)
            gemm_block<2>(gid & 1, gid >> 1,
                          dinh, dinl, 256, (const __nv_bfloat16*)nullptr, (const __nv_bfloat16*)nullptr, 0,
                          1 << 30, 256, wdh, wdl,
                          df, dynb, nullptr, nullptr, h0f, nullptr, 0.f, res_scale,
                          douh, doul, nullptr, nullptr);
    } else {
        int sid = bid - bid / 9 - 1;
        if (sid < NN / 8)
            spmm_block(sid * 8, hq, bhih, bhil);
    }
}

// ---------------- merged LN-cross + out GEMM + log_softmax ------------------
__device__ __forceinline__ float warp_sum(float v) {
#pragma unroll
    for (int off = 16; off; off >>= 1) v += __shfl_xor_sync(0xffffffffu, v, off);
    return v;
}

__global__ void __launch_bounds__(256) k_crossout(
    const float* __restrict__ h, const float* __restrict__ d,
    const float* __restrict__ g1, const float* __restrict__ b1,
    const float* __restrict__ g2, const float* __restrict__ b2,
    const float* __restrict__ Wout, const float* __restrict__ bout,
    float* __restrict__ out, float* __restrict__ cross_out)
{
    __shared__ float Ws[256 * 41];
    __shared__ float bs[NC];
    int t = threadIdx.x;
    for (int i = t; i < 256 * NC; i += 256) {
        int k = i / NC, c = i - k * NC;
        Ws[k * 41 + c] = Wout[i];
    }
    if (t < NC) bs[t] = bout[t];
    __syncthreads();

    int row = blockIdx.x * 8 + (t >> 5);
    int lane = t & 31;
    if (row >= NN) return;
    size_t rb = (size_t)row * H;

    float hv[8], dv[8];
#pragma unroll
    for (int r = 0; r < 8; r++) {
        int k = lane + 32 * r;
        hv[r] = h[rb + k];
        dv[r] = d[rb + k];
    }
    float sh = 0.f, sd = 0.f;
#pragma unroll
    for (int r = 0; r < 8; r++) { sh += hv[r]; sd += dv[r]; }
    sh = warp_sum(sh); sd = warp_sum(sd);
    float m1 = sh * (1.f / 256.f), m2 = sd * (1.f / 256.f);
    float q1 = 0.f, q2 = 0.f;
#pragma unroll
    for (int r = 0; r < 8; r++) {
        float e1 = hv[r] - m1; q1 += e1 * e1;
        float e2 = dv[r] - m2; q2 += e2 * e2;
    }
    q1 = warp_sum(q1); q2 = warp_sum(q2);
    float i1 = rsqrtf(q1 * (1.f / 256.f) + 1e-6f);
    float i2 = rsqrtf(q2 * (1.f / 256.f) + 1e-6f);

    float v[8];
#pragma unroll
    for (int r = 0; r < 8; r++) {
        int k = lane + 32 * r;
        v[r] = g1[k] * (hv[r] - m1) * i1 + b1[k] + g2[k] * (dv[r] - m2) * i2 + b2[k];
        if (cross_out) cross_out[rb + k] = v[r];
    }

    float acc[NC];
#pragma unroll
    for (int c = 0; c < NC; c++) acc[c] = 0.f;
#pragma unroll
    for (int r = 0; r < 8; r++) {
        int k = lane + 32 * r;
        const float* wr = &Ws[k * 41];
#pragma unroll
        for (int c = 0; c < NC; c++) acc[c] += v[r] * wr[c];
    }
#pragma unroll
    for (int c = 0; c < NC; c++)
#pragma unroll
        for (int off = 16; off; off >>= 1) acc[c] += __shfl_xor_sync(0xffffffffu, acc[c], off);

    float m = -1e30f;
#pragma unroll
    for (int c = 0; c < NC; c++) { acc[c] += bs[c]; m = fmaxf(m, acc[c]); }
    float s = 0.f;
#pragma unroll
    for (int c = 0; c < NC; c++) s += expf(acc[c] - m);
    float lse = m + logf(s);
    float* o = out + (size_t)row * NC;
#pragma unroll
    for (int c = 0; c < NC; c++)
        if ((c & 31) == lane) o[c] = acc[c] - lse;
}

// ---------------- launch ---------------------------------------------------
extern "C" void kernel_launch(void* const* d_in, const int* in_sizes, int n_in,
                              void* d_out, int out_size)
{
    const float* x     = (const float*)d_in[0];
    const int*   esrc  = (const int*)d_in[1];
    const int*   edst  = (const int*)d_in[2];
    const float* ew    = (const float*)d_in[3];
    const float* Wfc   = (const float*)d_in[4];
    const float* bfc   = (const float*)d_in[5];
    const float* convw = (const float*)d_in[6];
    const float* dynw  = (const float*)d_in[7];
    const float* dynb  = (const float*)d_in[8];
    const float* g1    = (const float*)d_in[9];
    const float* b1    = (const float*)d_in[10];
    const float* g2    = (const float*)d_in[11];
    const float* b2    = (const float*)d_in[12];
    const float* Wout  = (const float*)d_in[13];
    const float* bout  = (const float*)d_in[14];
    float* out = (float*)d_out;

    float *h0f, *hf, *df;
    __half* hq;
    cudaGetSymbolAddress((void**)&h0f, g_h0f);
    cudaGetSymbolAddress((void**)&hf,  g_hf);
    cudaGetSymbolAddress((void**)&df,  g_df);
    cudaGetSymbolAddress((void**)&hq,  g_hq);
    __nv_bfloat16 *bxh, *bxl, *bh0h, *bh0l, *bhih, *bhil, *bdAh, *bdAl, *bdBh, *bdBl, *w9h, *w9l, *wdh, *wdl;
    cudaGetSymbolAddress((void**)&bxh, g_bx_hi);
    cudaGetSymbolAddress((void**)&bxl, g_bx_lo);
    cudaGetSymbolAddress((void**)&bh0h, g_bh0_hi);
    cudaGetSymbolAddress((void**)&bh0l, g_bh0_lo);
    cudaGetSymbolAddress((void**)&bhih, g_bhi_hi);
    cudaGetSymbolAddress((void**)&bhil, g_bhi_lo);
    cudaGetSymbolAddress((void**)&bdAh, g_bdA_hi);
    cudaGetSymbolAddress((void**)&bdAl, g_bdA_lo);
    cudaGetSymbolAddress((void**)&bdBh, g_bdB_hi);
    cudaGetSymbolAddress((void**)&bdBl, g_bdB_lo);
    cudaGetSymbolAddress((void**)&w9h, g_wt9_hi);
    cudaGetSymbolAddress((void**)&w9l, g_wt9_lo);
    cudaGetSymbolAddress((void**)&wdh, g_wtd_hi);
    cudaGetSymbolAddress((void**)&wdl, g_wtd_lo);

    cudaFuncSetAttribute(k_gemm<0>, cudaFuncAttributeMaxDynamicSharedMemorySize, SMEM_TOTAL);
    cudaFuncSetAttribute(k_gemm<1>, cudaFuncAttributeMaxDynamicSharedMemorySize, SMEM_TOTAL);
    cudaFuncSetAttribute(k_sd,      cudaFuncAttributeMaxDynamicSharedMemorySize, SMEM_TOTAL);

    const int BIGK = 1 << 30;
    dim3 grid(2, GRID_M);

    // prep
    k_convx<<<(NN * 512 + 255) / 256, 256>>>(x);
    k_wprep9<<<(9 * 512 * 256 + 255) / 256, 256>>>(Wfc, convw);
    k_wprepd<<<(NL * 256 * 256 + 255) / 256, 256>>>(dynw);

    // fc: h = h0 = relu(x@Wfc + bfc); writes hf, h0f, bh0 pair, hq (fp16)
    k_gemm<0><<<grid, 256, SMEM_TOTAL>>>(
        bxh, bxl, 512, (const __nv_bfloat16*)nullptr, (const __nv_bfloat16*)nullptr, 0,
        BIGK, 512, w9h, w9l,
        hf, bfc, nullptr, nullptr, nullptr, nullptr, 0.f, 0.f,
        bh0h, bh0l, h0f, hq);

    // CSR build (independent of fc)
    k_zero<<<(NN + 255) / 256, 256>>>();
    k_hist<<<NE / 256, 256>>>(edst);
    k_scan1<<<98, 256>>>();
    k_scan2<<<1, 128>>>(98);
    k_scan3<<<98, 256>>>();
    k_scatter<<<NE / 256, 256>>>(esrc, edst, ew);

    for (int i = 0; i < NL; i++) {
        const __nv_bfloat16* dinh = (i == 0) ? bh0h : ((i & 1) ? bdAh : bdBh);
        const __nv_bfloat16* dinl = (i == 0) ? bh0l : ((i & 1) ? bdAl : bdBl);
        __nv_bfloat16* douh = (i & 1) ? bdBh : bdAh;
        __nv_bfloat16* doul = (i & 1) ? bdBl : bdAl;

        // fused: SpMM(hq -> bhi pair) overlapped with dyn GEMM (d -> d_next)
        k_sd<<<FUSED_GRID, 256, SMEM_TOTAL>>>(
            dinh, dinl, wdh + (size_t)i * 256 * 256, wdl + (size_t)i * 256 * 256,
            df, dynb + (size_t)i * H, h0f, (i > 0) ? 0.1f : 0.f,
            douh, doul,
            hq, bhih, bhil);

        float theta = logf(0.5f / (float)(i + 1) + 1.0f);
        // conv: h = relu(theta*([hi|h0]@convw_i) + (1-theta)*(0.9*hi+0.1*h0) + h)
        k_gemm<1><<<grid, 256, SMEM_TOTAL>>>(
            bhih, bhil, 256, bh0h, bh0l, 256,
            256, 512, w9h + (size_t)(1 + i) * 256 * 512, w9l + (size_t)(1 + i) * 256 * 512,
            hf, nullptr, bhih, bhil, h0f, hf, theta, 0.f,
            nullptr, nullptr, nullptr, hq);
    }

    float* cross_out_ptr = (out_size >= NN * (NC + H)) ? (out + (size_t)NN * NC) : nullptr;
    k_crossout<<<NN / 8, 256>>>(hf, df, g1, b1, g2, b2, Wout, bout, out, cross_out_ptr);
}